// round 11
// baseline (speedup 1.0000x reference)
#include <cuda_runtime.h>
#include <cuda_fp16.h>
#include <cstdint>

#define BB 2
#define TT 2048
#define DD 1024
#define HH 16
#define HDIM 64
#define QSTRIDE 8
#define MLPD 4096
#define NTOK (BB*TT)   // 4096
#define NGLOB (NTOK/QSTRIDE)   // 512 global query rows

// ---------------- scratch ----------------
__device__ __half g_xn[(size_t)NTOK*DD];
__device__ __half g_kv[(size_t)NTOK*2*DD];
__device__ __half g_q[(size_t)NGLOB*DD];
__device__ __half g_o[(size_t)NTOK*DD];
__device__ __half g_h[(size_t)NTOK*MLPD];
__device__ float  g_x1[(size_t)NTOK*DD];
__device__ __half g_wh[(size_t)12*1024*1024];   // w_in(3M) w_out(1M) w1(4M) w2(4M)

// ---------------- helpers ----------------
__device__ __forceinline__ uint32_t smem_u32(const void* p) {
    uint32_t a;
    asm("{ .reg .u64 t; cvta.to.shared.u64 t, %1; cvt.u32.u64 %0, t; }" : "=r"(a) : "l"(p));
    return a;
}
#define CP_ASYNC16(dst, src) \
    asm volatile("cp.async.cg.shared.global [%0], [%1], 16;" :: "r"(dst), "l"(src) : "memory")
#define CP_COMMIT() asm volatile("cp.async.commit_group;" ::: "memory")
#define CP_WAIT0() asm volatile("cp.async.wait_group 0;" ::: "memory")
#define CP_WAIT1() asm volatile("cp.async.wait_group 1;" ::: "memory")

#define LDSM_X4(r0, r1, r2, r3, addr) \
    asm volatile("ldmatrix.sync.aligned.m8n8.x4.shared.b16 {%0,%1,%2,%3}, [%4];" \
        : "=r"(r0), "=r"(r1), "=r"(r2), "=r"(r3) : "r"(addr))

__device__ __forceinline__ void mma_f16(float* d, const uint32_t* a, const uint32_t* b) {
    asm volatile(
        "mma.sync.aligned.m16n8k16.row.col.f32.f16.f16.f32 "
        "{%0,%1,%2,%3}, {%4,%5,%6,%7}, {%8,%9}, {%0,%1,%2,%3};"
        : "+f"(d[0]), "+f"(d[1]), "+f"(d[2]), "+f"(d[3])
        : "r"(a[0]), "r"(a[1]), "r"(a[2]), "r"(a[3]), "r"(b[0]), "r"(b[1]));
}

// ---------------- fp16 mma GEMM: C = A @ W.T + bias (+epi) ----------------
// A [M,K] half row-major (row r lives at flat row r*AR), W [N,K] half row-major.
// BM=BN=128, BK=64 halves. 256 threads = 8 warps 2(m)x4(n), warp tile 64x32. 2 CTA/SM.
#define ROWH 72
#define STG_B (128*ROWH*2)
#define STAGE_B (2*STG_B)
#define NSTG 3
#define SMEM_TOT (NSTG*STAGE_B)         // 110592 B -> 2 CTAs/SM

template <int EPI, int AR>  // EPI: 0=bias->half(+opt vout), 1=bias+residual->float, 2=bias+GELU->half
__global__ void __launch_bounds__(256, 2)
hgemm(const __half* __restrict__ A, const __half* __restrict__ W,
      const float* __restrict__ bias, const float* __restrict__ res,
      void* __restrict__ Cv, __half* __restrict__ vout, int voff,
      int M, int N, int K)
{
    extern __shared__ __half smem[];
    uint32_t sbase = smem_u32(smem);
    int tid = threadIdx.x;
    int wid = tid >> 5, lane = tid & 31;
    int gp = lane >> 2, tc = lane & 3;
    int m0 = blockIdx.y * 128, n0 = blockIdx.x * 128;
    int wm = (wid & 1) * 64;
    int wn = (wid >> 1) * 32;

    int a_row = lane & 15;
    int a_k8  = (lane >> 4) * 8;
    int b_grp = lane >> 3;
    int b_row = lane & 7;
    int b_nof = (b_grp >> 1) * 8 + b_row;
    int b_k8  = (b_grp & 1) * 8;

    float acc[4][4][4];
    #pragma unroll
    for (int i = 0; i < 4; i++)
        #pragma unroll
        for (int j = 0; j < 4; j++)
            #pragma unroll
            for (int k = 0; k < 4; k++) acc[i][j][k] = 0.f;

    const int KT = K >> 6;

    auto load_tile = [&](int s, int kt) {
        uint32_t sa = sbase + s * STAGE_B;
        uint32_t sb = sa + STG_B;
        const __half* Ag = A + kt * 64;
        const __half* Wg = W + (size_t)n0 * K + kt * 64;
        #pragma unroll
        for (int i = 0; i < 4; i++) {
            int idx = i * 256 + tid;
            int row = idx >> 3, ch = idx & 7;
            CP_ASYNC16(sa + (row * ROWH + ch * 8) * 2,
                       Ag + (size_t)(m0 + row) * AR * K + ch * 8);
        }
        #pragma unroll
        for (int i = 0; i < 4; i++) {
            int idx = i * 256 + tid;
            int row = idx >> 3, ch = idx & 7;
            CP_ASYNC16(sb + (row * ROWH + ch * 8) * 2, Wg + (size_t)row * K + ch * 8);
        }
        CP_COMMIT();
    };

    load_tile(0, 0);
    load_tile(1, 1);

    for (int kt = 0; kt < KT; kt++) {
        if (kt + 1 < KT) { CP_WAIT1(); } else { CP_WAIT0(); }
        __syncthreads();
        if (kt + 2 < KT) load_tile((kt + 2) % NSTG, kt + 2);

        uint32_t sa = sbase + (kt % NSTG) * STAGE_B;
        uint32_t sb = sa + STG_B;

        #pragma unroll
        for (int ks = 0; ks < 4; ks++) {
            uint32_t af[4][4], bf[2][4];
            #pragma unroll
            for (int mt = 0; mt < 4; mt++)
                LDSM_X4(af[mt][0], af[mt][1], af[mt][2], af[mt][3],
                        sa + ((wm + mt * 16 + a_row) * ROWH + ks * 16 + a_k8) * 2);
            #pragma unroll
            for (int p = 0; p < 2; p++)
                LDSM_X4(bf[p][0], bf[p][1], bf[p][2], bf[p][3],
                        sb + ((wn + p * 16 + b_nof) * ROWH + ks * 16 + b_k8) * 2);
            #pragma unroll
            for (int mt = 0; mt < 4; mt++)
                #pragma unroll
                for (int nt = 0; nt < 4; nt++)
                    mma_f16(acc[mt][nt], af[mt], &bf[nt >> 1][(nt & 1) * 2]);
        }
    }

    // epilogue (writes at compact row index)
    #pragma unroll
    for (int mt = 0; mt < 4; mt++) {
        int r0 = m0 + wm + mt * 16 + gp;
        #pragma unroll
        for (int nt = 0; nt < 4; nt++) {
            int c = n0 + wn + nt * 8 + 2 * tc;
            float bx = bias[c], by = bias[c + 1];
            #pragma unroll
            for (int half_ = 0; half_ < 2; half_++) {
                int r = r0 + half_ * 8;
                float vx = acc[mt][nt][half_ * 2 + 0] + bx;
                float vy = acc[mt][nt][half_ * 2 + 1] + by;
                size_t off = (size_t)r * N + c;
                if (EPI == 1) {
                    float2 rr = *(const float2*)(res + off);
                    vx += rr.x; vy += rr.y;
                    float2 o2; o2.x = vx; o2.y = vy;
                    *(float2*)((float*)Cv + off) = o2;
                } else {
                    if (EPI == 2) {
                        vx = 0.5f * vx * (1.0f + erff(vx * 0.70710678118f));
                        vy = 0.5f * vy * (1.0f + erff(vy * 0.70710678118f));
                    }
                    __half2 hv = __floats2half2_rn(vx, vy);
                    *(__half2*)((__half*)Cv + off) = hv;
                    if (EPI == 0 && vout != nullptr && c >= voff) {
                        // fused v -> o copy (attention output = v for non-global rows)
                        *(__half2*)(vout + (size_t)r * DD + (c - voff)) = hv;
                    }
                }
            }
        }
    }
}

// ---------------- LayerNorm (float in, half out) ----------------
__global__ void ln_kernel(const float* __restrict__ x, const float* __restrict__ g,
                          const float* __restrict__ b, __half* __restrict__ out) {
    int row = blockIdx.x;
    int tid = threadIdx.x;
    const float4* xr = (const float4*)(x + (size_t)row * DD);
    float4 v = xr[tid];
    float s  = v.x + v.y + v.z + v.w;
    float ss = v.x*v.x + v.y*v.y + v.z*v.z + v.w*v.w;
    #pragma unroll
    for (int o = 16; o; o >>= 1) {
        s  += __shfl_xor_sync(0xffffffffu, s,  o);
        ss += __shfl_xor_sync(0xffffffffu, ss, o);
    }
    __shared__ float sm[8], sm2[8];
    int w = tid >> 5, l = tid & 31;
    if (l == 0) { sm[w] = s; sm2[w] = ss; }
    __syncthreads();
    float tot = 0.f, tot2 = 0.f;
    #pragma unroll
    for (int i = 0; i < 8; i++) { tot += sm[i]; tot2 += sm2[i]; }
    float mean = tot * (1.0f / DD);
    float var  = tot2 * (1.0f / DD) - mean * mean;
    float rstd = rsqrtf(var + 1e-5f);
    float4 gg = ((const float4*)g)[tid];
    float4 bb = ((const float4*)b)[tid];
    __half2 h0 = __floats2half2_rn((v.x - mean) * rstd * gg.x + bb.x,
                                   (v.y - mean) * rstd * gg.y + bb.y);
    __half2 h1 = __floats2half2_rn((v.z - mean) * rstd * gg.z + bb.z,
                                   (v.w - mean) * rstd * gg.w + bb.w);
    uint2 u;
    u.x = *(uint32_t*)&h0; u.y = *(uint32_t*)&h1;
    ((uint2*)(out + (size_t)row * DD))[tid] = u;
}

// ---------------- convert ALL weights float -> half (one kernel) ----------------
// segments (in float4 units): w_in 786432 | w_out 262144 | w1 1048576 | w2 1048576
#define CVT_N0 786432
#define CVT_N1 (CVT_N0 + 262144)
#define CVT_N2 (CVT_N1 + 1048576)
#define CVT_N3 (CVT_N2 + 1048576)
__global__ void cvt_all_kernel(const float* __restrict__ w_in, const float* __restrict__ w_out,
                               const float* __restrict__ w1, const float* __restrict__ w2,
                               __half* __restrict__ oh) {
    int i = blockIdx.x * blockDim.x + threadIdx.x;
    if (i >= CVT_N3) return;
    const float* src; int j;
    if (i < CVT_N0)      { src = w_in;  j = i; }
    else if (i < CVT_N1) { src = w_out; j = i - CVT_N0; }
    else if (i < CVT_N2) { src = w1;    j = i - CVT_N1; }
    else                 { src = w2;    j = i - CVT_N2; }
    float4 v = ((const float4*)src)[j];
    __half2 h0 = __floats2half2_rn(v.x, v.y);
    __half2 h1 = __floats2half2_rn(v.z, v.w);
    uint2 u; u.x = *(uint32_t*)&h0; u.y = *(uint32_t*)&h1;
    ((uint2*)oh)[i] = u;
}

// ---------------- global-row attention (compact Q; K/V from kv buffer) ----------
__global__ void __launch_bounds__(256)
attn_kernel(const __half* __restrict__ qbuf, const __half* __restrict__ kv,
            __half* __restrict__ o) {
    int bid = blockIdx.x;
    int qt = bid & 7;
    int h  = (bid >> 3) & 15;
    int b  = bid >> 7;

    __shared__ float Qs[32][68];
    __shared__ float Ks[32][68];
    __shared__ float Vs[32][68];
    __shared__ float S [32][36];

    int tid = threadIdx.x;
    int qi_ = tid >> 3, d8 = tid & 7;

    {
        int g = b * 256 + qt * 32 + qi_;     // compact global-query row
        uint4 u = *(const uint4*)(qbuf + (size_t)g * DD + h * HDIM + d8 * 8);
        const __half2* hp = (const __half2*)&u;
        #pragma unroll
        for (int j = 0; j < 4; j++) {
            float2 f = __half22float2(hp[j]);
            Qs[qi_][d8 * 8 + j * 2]     = f.x * 0.125f;
            Qs[qi_][d8 * 8 + j * 2 + 1] = f.y * 0.125f;
        }
    }
    __syncthreads();

    int qi = tid >> 3, sl = tid & 7;
    float mrun = -1e30f, lrun = 0.f;
    float oacc[8] = {};

    for (int kt = 0; kt < TT / 32; kt++) {
        {
            size_t base = (size_t)(b * TT + kt * 32 + qi_) * (2 * DD) + h * HDIM + d8 * 8;
            uint4 uk = *(const uint4*)(kv + base);
            uint4 uv = *(const uint4*)(kv + base + DD);
            const __half2* kp = (const __half2*)&uk;
            const __half2* vp = (const __half2*)&uv;
            #pragma unroll
            for (int j = 0; j < 4; j++) {
                float2 fk = __half22float2(kp[j]);
                float2 fv = __half22float2(vp[j]);
                Ks[qi_][d8 * 8 + j * 2] = fk.x;  Ks[qi_][d8 * 8 + j * 2 + 1] = fk.y;
                Vs[qi_][d8 * 8 + j * 2] = fv.x;  Vs[qi_][d8 * 8 + j * 2 + 1] = fv.y;
            }
        }
        __syncthreads();

        float s4[4] = {0.f, 0.f, 0.f, 0.f};
        #pragma unroll
        for (int d4 = 0; d4 < 16; d4++) {
            float4 qv = *(const float4*)&Qs[qi][d4 * 4];
            #pragma unroll
            for (int kj = 0; kj < 4; kj++) {
                float4 kvv = *(const float4*)&Ks[kj * 8 + sl][d4 * 4];
                s4[kj] += qv.x * kvv.x + qv.y * kvv.y + qv.z * kvv.z + qv.w * kvv.w;
            }
        }
        float tmax = fmaxf(fmaxf(s4[0], s4[1]), fmaxf(s4[2], s4[3]));
        #pragma unroll
        for (int off = 4; off; off >>= 1)
            tmax = fmaxf(tmax, __shfl_xor_sync(0xffffffffu, tmax, off));
        float mnew = fmaxf(mrun, tmax);
        float psum = 0.f;
        #pragma unroll
        for (int kj = 0; kj < 4; kj++) {
            float p = __expf(s4[kj] - mnew);
            psum += p;
            S[qi][kj * 8 + sl] = p;
        }
        #pragma unroll
        for (int off = 4; off; off >>= 1)
            psum += __shfl_xor_sync(0xffffffffu, psum, off);
        float factor = __expf(mrun - mnew);
        lrun = lrun * factor + psum;
        mrun = mnew;
        __syncwarp();

        #pragma unroll
        for (int j = 0; j < 8; j++) oacc[j] *= factor;
        #pragma unroll
        for (int key = 0; key < 32; key++) {
            float p = S[qi][key];
            float4 v0 = *(const float4*)&Vs[key][sl * 8];
            float4 v1 = *(const float4*)&Vs[key][sl * 8 + 4];
            oacc[0] += p * v0.x; oacc[1] += p * v0.y;
            oacc[2] += p * v0.z; oacc[3] += p * v0.w;
            oacc[4] += p * v1.x; oacc[5] += p * v1.y;
            oacc[6] += p * v1.z; oacc[7] += p * v1.w;
        }
        __syncthreads();
    }

    float inv = 1.0f / lrun;
    int t = (qt * 32 + qi) * QSTRIDE;
    __half2 h0 = __floats2half2_rn(oacc[0] * inv, oacc[1] * inv);
    __half2 h1 = __floats2half2_rn(oacc[2] * inv, oacc[3] * inv);
    __half2 h2 = __floats2half2_rn(oacc[4] * inv, oacc[5] * inv);
    __half2 h3 = __floats2half2_rn(oacc[6] * inv, oacc[7] * inv);
    uint4 u;
    u.x = *(uint32_t*)&h0; u.y = *(uint32_t*)&h1;
    u.z = *(uint32_t*)&h2; u.w = *(uint32_t*)&h3;
    *(uint4*)(o + (size_t)(b * TT + t) * DD + h * HDIM + sl * 8) = u;
}

// ---------------- launch ----------------
extern "C" void kernel_launch(void* const* d_in, const int* in_sizes, int n_in,
                              void* d_out, int out_size) {
    const float* x     = (const float*)d_in[0];
    const float* w_in  = (const float*)d_in[1];
    const float* b_in  = (const float*)d_in[2];
    const float* w_out = (const float*)d_in[3];
    const float* b_out = (const float*)d_in[4];
    const float* w1    = (const float*)d_in[5];
    const float* b1    = (const float*)d_in[6];
    const float* w2    = (const float*)d_in[7];
    const float* b2    = (const float*)d_in[8];
    const float* ln1g  = (const float*)d_in[9];
    const float* ln1b  = (const float*)d_in[10];
    const float* ln2g  = (const float*)d_in[11];
    const float* ln2b  = (const float*)d_in[12];
    float* out = (float*)d_out;

    __half *xn, *kvb, *qb, *o, *hbuf, *wh;
    float *x1;
    cudaGetSymbolAddress((void**)&xn,   g_xn);
    cudaGetSymbolAddress((void**)&kvb,  g_kv);
    cudaGetSymbolAddress((void**)&qb,   g_q);
    cudaGetSymbolAddress((void**)&o,    g_o);
    cudaGetSymbolAddress((void**)&hbuf, g_h);
    cudaGetSymbolAddress((void**)&x1,   g_x1);
    cudaGetSymbolAddress((void**)&wh,   g_wh);
    __half* wh_q   = wh;                              // w_in rows 0..D      (Q)
    __half* wh_kv  = wh + (size_t)DD*DD;              // w_in rows D..3D     (K,V)
    __half* wh_out = wh + (size_t)3*1024*1024;
    __half* wh_1   = wh + (size_t)4*1024*1024;
    __half* wh_2   = wh + (size_t)8*1024*1024;

    cudaFuncSetAttribute(hgemm<0,1>, cudaFuncAttributeMaxDynamicSharedMemorySize, SMEM_TOT);
    cudaFuncSetAttribute(hgemm<0,8>, cudaFuncAttributeMaxDynamicSharedMemorySize, SMEM_TOT);
    cudaFuncSetAttribute(hgemm<1,1>, cudaFuncAttributeMaxDynamicSharedMemorySize, SMEM_TOT);
    cudaFuncSetAttribute(hgemm<2,1>, cudaFuncAttributeMaxDynamicSharedMemorySize, SMEM_TOT);

    // 0) convert all weights to half (single kernel)
    cvt_all_kernel<<<(CVT_N3 + 255)/256, 256>>>(w_in, w_out, w1, w2, wh);
    // 1) LN1 -> half
    ln_kernel<<<NTOK, 256>>>(x, ln1g, ln1b, xn);
    // 2) kv = xn @ w_in[D:3D].T + b_in[D:3D]  (half; V columns fused-copied into o)
    hgemm<0,1><<<dim3(2*DD/128, NTOK/128), 256, SMEM_TOT>>>(
        xn, wh_kv, b_in + DD, nullptr, kvb, o, DD, NTOK, 2*DD, DD);
    // 3) q (global rows only, gathered: compact row g <- flat row 8g)
    hgemm<0,8><<<dim3(DD/128, NGLOB/128), 256, SMEM_TOT>>>(
        xn, wh_q, b_in, nullptr, qb, nullptr, 0, NGLOB, DD, DD);
    // 4) attention (overwrites the global rows of o)
    attn_kernel<<<BB*HH*8, 256>>>(qb, kvb, o);
    // 5) x1 = o @ w_out.T + b_out + x  (float out)
    hgemm<1,1><<<dim3(DD/128, NTOK/128), 256, SMEM_TOT>>>(
        o, wh_out, b_out, x, x1, nullptr, 0, NTOK, DD, DD);
    // 6) LN2 -> half
    ln_kernel<<<NTOK, 256>>>(x1, ln2g, ln2b, xn);
    // 7) h = gelu(xn @ w1.T + b1)  (half out)
    hgemm<2,1><<<dim3(MLPD/128, NTOK/128), 256, SMEM_TOT>>>(
        xn, wh_1, b1, nullptr, hbuf, nullptr, 0, NTOK, MLPD, DD);
    // 8) out = h @ w2.T + b2 + x1  (float out)
    hgemm<1,1><<<dim3(DD/128, NTOK/128), 256, SMEM_TOT>>>(
        hbuf, wh_2, b2, x1, out, nullptr, 0, NTOK, DD, MLPD);
}

// round 12
// speedup vs baseline: 1.5779x; 1.5779x over previous
#include <cuda_runtime.h>
#include <cuda_fp16.h>
#include <cstdint>

#define BB 2
#define TT 2048
#define DD 1024
#define HH 16
#define HDIM 64
#define QSTRIDE 8
#define MLPD 4096
#define NTOK (BB*TT)   // 4096
#define NGLOB (NTOK/QSTRIDE)   // 512

// ---------------- scratch ----------------
__device__ __half g_xn[(size_t)NTOK*DD];
__device__ __half g_kv[(size_t)NTOK*2*DD];
__device__ __half g_q[(size_t)NGLOB*DD];
__device__ __half g_o[(size_t)NTOK*DD];
__device__ __half g_h[(size_t)NTOK*MLPD];
__device__ float  g_x1[(size_t)NTOK*DD];
__device__ __half g_wh[(size_t)12*1024*1024];   // w_in(3M) w_out(1M) w1(4M) w2(4M)

// ---------------- helpers ----------------
__device__ __forceinline__ uint32_t smem_u32(const void* p) {
    uint32_t a;
    asm("{ .reg .u64 t; cvta.to.shared.u64 t, %1; cvt.u32.u64 %0, t; }" : "=r"(a) : "l"(p));
    return a;
}
#define CP_ASYNC16(dst, src) \
    asm volatile("cp.async.cg.shared.global [%0], [%1], 16;" :: "r"(dst), "l"(src) : "memory")
#define CP_COMMIT() asm volatile("cp.async.commit_group;" ::: "memory")
#define CP_WAIT0() asm volatile("cp.async.wait_group 0;" ::: "memory")
#define CP_WAIT1() asm volatile("cp.async.wait_group 1;" ::: "memory")

#define LDSM_X4(r0, r1, r2, r3, addr) \
    asm volatile("ldmatrix.sync.aligned.m8n8.x4.shared.b16 {%0,%1,%2,%3}, [%4];" \
        : "=r"(r0), "=r"(r1), "=r"(r2), "=r"(r3) : "r"(addr))

__device__ __forceinline__ void mma_f16(float* d, const uint32_t* a, const uint32_t* b) {
    asm volatile(
        "mma.sync.aligned.m16n8k16.row.col.f32.f16.f16.f32 "
        "{%0,%1,%2,%3}, {%4,%5,%6,%7}, {%8,%9}, {%0,%1,%2,%3};"
        : "+f"(d[0]), "+f"(d[1]), "+f"(d[2]), "+f"(d[3])
        : "r"(a[0]), "r"(a[1]), "r"(a[2]), "r"(a[3]), "r"(b[0]), "r"(b[1]));
}

// ---------------- fp16 mma GEMM (R10 codegen): C = A @ W.T + bias (+epi) -------
// BM=BN=128, BK=64 halves. 256 threads = 8 warps 2(m)x4(n), warp tile 64x32. 2 CTA/SM.
#define ROWH 72
#define STG_B (128*ROWH*2)
#define STAGE_B (2*STG_B)
#define NSTG 3
#define SMEM_TOT (NSTG*STAGE_B)         // 110592 B -> 2 CTAs/SM

template <int EPI>  // 0=bias->half(+opt vout for c>=DD), 1=bias+residual->float, 2=bias+GELU->half
__global__ void __launch_bounds__(256, 2)
hgemm(const __half* __restrict__ A, const __half* __restrict__ W,
      const float* __restrict__ bias, const float* __restrict__ res,
      void* __restrict__ Cv, __half* __restrict__ vout, int M, int N, int K)
{
    extern __shared__ __half smem[];
    uint32_t sbase = smem_u32(smem);
    int tid = threadIdx.x;
    int wid = tid >> 5, lane = tid & 31;
    int gp = lane >> 2, tc = lane & 3;
    int m0 = blockIdx.y * 128, n0 = blockIdx.x * 128;
    int wm = (wid & 1) * 64;
    int wn = (wid >> 1) * 32;

    int a_row = lane & 15;
    int a_k8  = (lane >> 4) * 8;
    int b_grp = lane >> 3;
    int b_row = lane & 7;
    int b_nof = (b_grp >> 1) * 8 + b_row;
    int b_k8  = (b_grp & 1) * 8;

    float acc[4][4][4];
    #pragma unroll
    for (int i = 0; i < 4; i++)
        #pragma unroll
        for (int j = 0; j < 4; j++)
            #pragma unroll
            for (int k = 0; k < 4; k++) acc[i][j][k] = 0.f;

    const int KT = K >> 6;

    auto load_tile = [&](int s, int kt) {
        uint32_t sa = sbase + s * STAGE_B;
        uint32_t sb = sa + STG_B;
        const __half* Ag = A + (size_t)m0 * K + kt * 64;
        const __half* Wg = W + (size_t)n0 * K + kt * 64;
        #pragma unroll
        for (int i = 0; i < 4; i++) {
            int idx = i * 256 + tid;
            int row = idx >> 3, ch = idx & 7;
            CP_ASYNC16(sa + (row * ROWH + ch * 8) * 2, Ag + (size_t)row * K + ch * 8);
        }
        #pragma unroll
        for (int i = 0; i < 4; i++) {
            int idx = i * 256 + tid;
            int row = idx >> 3, ch = idx & 7;
            CP_ASYNC16(sb + (row * ROWH + ch * 8) * 2, Wg + (size_t)row * K + ch * 8);
        }
        CP_COMMIT();
    };

    load_tile(0, 0);
    load_tile(1, 1);

    for (int kt = 0; kt < KT; kt++) {
        if (kt + 1 < KT) { CP_WAIT1(); } else { CP_WAIT0(); }
        __syncthreads();
        if (kt + 2 < KT) load_tile((kt + 2) % NSTG, kt + 2);

        uint32_t sa = sbase + (kt % NSTG) * STAGE_B;
        uint32_t sb = sa + STG_B;

        #pragma unroll
        for (int ks = 0; ks < 4; ks++) {
            uint32_t af[4][4], bf[2][4];
            #pragma unroll
            for (int mt = 0; mt < 4; mt++)
                LDSM_X4(af[mt][0], af[mt][1], af[mt][2], af[mt][3],
                        sa + ((wm + mt * 16 + a_row) * ROWH + ks * 16 + a_k8) * 2);
            #pragma unroll
            for (int p = 0; p < 2; p++)
                LDSM_X4(bf[p][0], bf[p][1], bf[p][2], bf[p][3],
                        sb + ((wn + p * 16 + b_nof) * ROWH + ks * 16 + b_k8) * 2);
            #pragma unroll
            for (int mt = 0; mt < 4; mt++)
                #pragma unroll
                for (int nt = 0; nt < 4; nt++)
                    mma_f16(acc[mt][nt], af[mt], &bf[nt >> 1][(nt & 1) * 2]);
        }
    }

    // epilogue
    #pragma unroll
    for (int mt = 0; mt < 4; mt++) {
        int r0 = m0 + wm + mt * 16 + gp;
        #pragma unroll
        for (int nt = 0; nt < 4; nt++) {
            int c = n0 + wn + nt * 8 + 2 * tc;
            float bx = bias[c], by = bias[c + 1];
            #pragma unroll
            for (int half_ = 0; half_ < 2; half_++) {
                int r = r0 + half_ * 8;
                float vx = acc[mt][nt][half_ * 2 + 0] + bx;
                float vy = acc[mt][nt][half_ * 2 + 1] + by;
                size_t off = (size_t)r * N + c;
                if (EPI == 1) {
                    float2 rr = *(const float2*)(res + off);
                    vx += rr.x; vy += rr.y;
                    float2 o2; o2.x = vx; o2.y = vy;
                    *(float2*)((float*)Cv + off) = o2;
                } else {
                    if (EPI == 2) {
                        vx = 0.5f * vx * (1.0f + erff(vx * 0.70710678118f));
                        vy = 0.5f * vy * (1.0f + erff(vy * 0.70710678118f));
                    }
                    __half2 hv = __floats2half2_rn(vx, vy);
                    *(__half2*)((__half*)Cv + off) = hv;
                    if (EPI == 0 && vout != nullptr && c >= DD) {
                        // fused v -> o copy (attention output = v for non-global rows)
                        *(__half2*)(vout + (size_t)r * DD + (c - DD)) = hv;
                    }
                }
            }
        }
    }
}

// ---------------- standalone Q GEMM: qb[g] = xn[8g] @ Wq.T + bq ---------------
// M=512 (gathered, stride 8 rows), N=1024, K=1024. Own codegen (isolated regs).
__global__ void __launch_bounds__(256, 2)
qgemm(const __half* __restrict__ A, const __half* __restrict__ W,
      const float* __restrict__ bias, __half* __restrict__ C)
{
    extern __shared__ __half smem[];
    uint32_t sbase = smem_u32(smem);
    const int K = DD, N = DD;
    int tid = threadIdx.x;
    int wid = tid >> 5, lane = tid & 31;
    int gp = lane >> 2, tc = lane & 3;
    int m0 = blockIdx.y * 128, n0 = blockIdx.x * 128;
    int wm = (wid & 1) * 64;
    int wn = (wid >> 1) * 32;

    int a_row = lane & 15;
    int a_k8  = (lane >> 4) * 8;
    int b_grp = lane >> 3;
    int b_row = lane & 7;
    int b_nof = (b_grp >> 1) * 8 + b_row;
    int b_k8  = (b_grp & 1) * 8;

    float acc[4][4][4];
    #pragma unroll
    for (int i = 0; i < 4; i++)
        #pragma unroll
        for (int j = 0; j < 4; j++)
            #pragma unroll
            for (int k = 0; k < 4; k++) acc[i][j][k] = 0.f;

    const int KT = K >> 6;

    auto load_tile = [&](int s, int kt) {
        uint32_t sa = sbase + s * STAGE_B;
        uint32_t sb = sa + STG_B;
        const __half* Ag = A + kt * 64;
        const __half* Wg = W + (size_t)n0 * K + kt * 64;
        #pragma unroll
        for (int i = 0; i < 4; i++) {
            int idx = i * 256 + tid;
            int row = idx >> 3, ch = idx & 7;
            CP_ASYNC16(sa + (row * ROWH + ch * 8) * 2,
                       Ag + (size_t)(m0 + row) * (QSTRIDE * DD) + ch * 8);
        }
        #pragma unroll
        for (int i = 0; i < 4; i++) {
            int idx = i * 256 + tid;
            int row = idx >> 3, ch = idx & 7;
            CP_ASYNC16(sb + (row * ROWH + ch * 8) * 2, Wg + (size_t)row * K + ch * 8);
        }
        CP_COMMIT();
    };

    load_tile(0, 0);
    load_tile(1, 1);

    for (int kt = 0; kt < KT; kt++) {
        if (kt + 1 < KT) { CP_WAIT1(); } else { CP_WAIT0(); }
        __syncthreads();
        if (kt + 2 < KT) load_tile((kt + 2) % NSTG, kt + 2);

        uint32_t sa = sbase + (kt % NSTG) * STAGE_B;
        uint32_t sb = sa + STG_B;

        #pragma unroll
        for (int ks = 0; ks < 4; ks++) {
            uint32_t af[4][4], bf[2][4];
            #pragma unroll
            for (int mt = 0; mt < 4; mt++)
                LDSM_X4(af[mt][0], af[mt][1], af[mt][2], af[mt][3],
                        sa + ((wm + mt * 16 + a_row) * ROWH + ks * 16 + a_k8) * 2);
            #pragma unroll
            for (int p = 0; p < 2; p++)
                LDSM_X4(bf[p][0], bf[p][1], bf[p][2], bf[p][3],
                        sb + ((wn + p * 16 + b_nof) * ROWH + ks * 16 + b_k8) * 2);
            #pragma unroll
            for (int mt = 0; mt < 4; mt++)
                #pragma unroll
                for (int nt = 0; nt < 4; nt++)
                    mma_f16(acc[mt][nt], af[mt], &bf[nt >> 1][(nt & 1) * 2]);
        }
    }

    #pragma unroll
    for (int mt = 0; mt < 4; mt++) {
        int r0 = m0 + wm + mt * 16 + gp;
        #pragma unroll
        for (int nt = 0; nt < 4; nt++) {
            int c = n0 + wn + nt * 8 + 2 * tc;
            float bx = bias[c], by = bias[c + 1];
            #pragma unroll
            for (int half_ = 0; half_ < 2; half_++) {
                int r = r0 + half_ * 8;
                float vx = acc[mt][nt][half_ * 2 + 0] + bx;
                float vy = acc[mt][nt][half_ * 2 + 1] + by;
                *(__half2*)(C + (size_t)r * N + c) = __floats2half2_rn(vx, vy);
            }
        }
    }
}

// ---------------- LayerNorm (float in, half out) ----------------
__global__ void ln_kernel(const float* __restrict__ x, const float* __restrict__ g,
                          const float* __restrict__ b, __half* __restrict__ out) {
    int row = blockIdx.x;
    int tid = threadIdx.x;
    const float4* xr = (const float4*)(x + (size_t)row * DD);
    float4 v = xr[tid];
    float s  = v.x + v.y + v.z + v.w;
    float ss = v.x*v.x + v.y*v.y + v.z*v.z + v.w*v.w;
    #pragma unroll
    for (int o = 16; o; o >>= 1) {
        s  += __shfl_xor_sync(0xffffffffu, s,  o);
        ss += __shfl_xor_sync(0xffffffffu, ss, o);
    }
    __shared__ float sm[8], sm2[8];
    int w = tid >> 5, l = tid & 31;
    if (l == 0) { sm[w] = s; sm2[w] = ss; }
    __syncthreads();
    float tot = 0.f, tot2 = 0.f;
    #pragma unroll
    for (int i = 0; i < 8; i++) { tot += sm[i]; tot2 += sm2[i]; }
    float mean = tot * (1.0f / DD);
    float var  = tot2 * (1.0f / DD) - mean * mean;
    float rstd = rsqrtf(var + 1e-5f);
    float4 gg = ((const float4*)g)[tid];
    float4 bb = ((const float4*)b)[tid];
    __half2 h0 = __floats2half2_rn((v.x - mean) * rstd * gg.x + bb.x,
                                   (v.y - mean) * rstd * gg.y + bb.y);
    __half2 h1 = __floats2half2_rn((v.z - mean) * rstd * gg.z + bb.z,
                                   (v.w - mean) * rstd * gg.w + bb.w);
    uint2 u;
    u.x = *(uint32_t*)&h0; u.y = *(uint32_t*)&h1;
    ((uint2*)(out + (size_t)row * DD))[tid] = u;
}

// ---------------- convert weights float -> half ----------------
__global__ void cvt_kernel(const float* __restrict__ in, __half* __restrict__ out, int n4) {
    int i = blockIdx.x * blockDim.x + threadIdx.x;
    if (i >= n4) return;
    float4 v = ((const float4*)in)[i];
    __half2 h0 = __floats2half2_rn(v.x, v.y);
    __half2 h1 = __floats2half2_rn(v.z, v.w);
    uint2 u; u.x = *(uint32_t*)&h0; u.y = *(uint32_t*)&h1;
    ((uint2*)out)[i] = u;
}

// ---------------- global-row attention (compact Q; K/V from kv buffer) ----------
__global__ void __launch_bounds__(256)
attn_kernel(const __half* __restrict__ qbuf, const __half* __restrict__ kv,
            __half* __restrict__ o) {
    int bid = blockIdx.x;
    int qt = bid & 7;
    int h  = (bid >> 3) & 15;
    int b  = bid >> 7;

    __shared__ float Qs[32][68];
    __shared__ float Ks[32][68];
    __shared__ float Vs[32][68];
    __shared__ float S [32][36];

    int tid = threadIdx.x;
    int qi_ = tid >> 3, d8 = tid & 7;

    {
        int g = b * 256 + qt * 32 + qi_;
        uint4 u = *(const uint4*)(qbuf + (size_t)g * DD + h * HDIM + d8 * 8);
        const __half2* hp = (const __half2*)&u;
        #pragma unroll
        for (int j = 0; j < 4; j++) {
            float2 f = __half22float2(hp[j]);
            Qs[qi_][d8 * 8 + j * 2]     = f.x * 0.125f;
            Qs[qi_][d8 * 8 + j * 2 + 1] = f.y * 0.125f;
        }
    }
    __syncthreads();

    int qi = tid >> 3, sl = tid & 7;
    float mrun = -1e30f, lrun = 0.f;
    float oacc[8] = {};

    for (int kt = 0; kt < TT / 32; kt++) {
        {
            size_t base = (size_t)(b * TT + kt * 32 + qi_) * (2 * DD) + h * HDIM + d8 * 8;
            uint4 uk = *(const uint4*)(kv + base);
            uint4 uv = *(const uint4*)(kv + base + DD);
            const __half2* kp = (const __half2*)&uk;
            const __half2* vp = (const __half2*)&uv;
            #pragma unroll
            for (int j = 0; j < 4; j++) {
                float2 fk = __half22float2(kp[j]);
                float2 fv = __half22float2(vp[j]);
                Ks[qi_][d8 * 8 + j * 2] = fk.x;  Ks[qi_][d8 * 8 + j * 2 + 1] = fk.y;
                Vs[qi_][d8 * 8 + j * 2] = fv.x;  Vs[qi_][d8 * 8 + j * 2 + 1] = fv.y;
            }
        }
        __syncthreads();

        float s4[4] = {0.f, 0.f, 0.f, 0.f};
        #pragma unroll
        for (int d4 = 0; d4 < 16; d4++) {
            float4 qv = *(const float4*)&Qs[qi][d4 * 4];
            #pragma unroll
            for (int kj = 0; kj < 4; kj++) {
                float4 kvv = *(const float4*)&Ks[kj * 8 + sl][d4 * 4];
                s4[kj] += qv.x * kvv.x + qv.y * kvv.y + qv.z * kvv.z + qv.w * kvv.w;
            }
        }
        float tmax = fmaxf(fmaxf(s4[0], s4[1]), fmaxf(s4[2], s4[3]));
        #pragma unroll
        for (int off = 4; off; off >>= 1)
            tmax = fmaxf(tmax, __shfl_xor_sync(0xffffffffu, tmax, off));
        float mnew = fmaxf(mrun, tmax);
        float psum = 0.f;
        #pragma unroll
        for (int kj = 0; kj < 4; kj++) {
            float p = __expf(s4[kj] - mnew);
            psum += p;
            S[qi][kj * 8 + sl] = p;
        }
        #pragma unroll
        for (int off = 4; off; off >>= 1)
            psum += __shfl_xor_sync(0xffffffffu, psum, off);
        float factor = __expf(mrun - mnew);
        lrun = lrun * factor + psum;
        mrun = mnew;
        __syncwarp();

        #pragma unroll
        for (int j = 0; j < 8; j++) oacc[j] *= factor;
        #pragma unroll
        for (int key = 0; key < 32; key++) {
            float p = S[qi][key];
            float4 v0 = *(const float4*)&Vs[key][sl * 8];
            float4 v1 = *(const float4*)&Vs[key][sl * 8 + 4];
            oacc[0] += p * v0.x; oacc[1] += p * v0.y;
            oacc[2] += p * v0.z; oacc[3] += p * v0.w;
            oacc[4] += p * v1.x; oacc[5] += p * v1.y;
            oacc[6] += p * v1.z; oacc[7] += p * v1.w;
        }
        __syncthreads();
    }

    float inv = 1.0f / lrun;
    int t = (qt * 32 + qi) * QSTRIDE;
    __half2 h0 = __floats2half2_rn(oacc[0] * inv, oacc[1] * inv);
    __half2 h1 = __floats2half2_rn(oacc[2] * inv, oacc[3] * inv);
    __half2 h2 = __floats2half2_rn(oacc[4] * inv, oacc[5] * inv);
    __half2 h3 = __floats2half2_rn(oacc[6] * inv, oacc[7] * inv);
    uint4 u;
    u.x = *(uint32_t*)&h0; u.y = *(uint32_t*)&h1;
    u.z = *(uint32_t*)&h2; u.w = *(uint32_t*)&h3;
    *(uint4*)(o + (size_t)(b * TT + t) * DD + h * HDIM + sl * 8) = u;
}

// ---------------- launch ----------------
extern "C" void kernel_launch(void* const* d_in, const int* in_sizes, int n_in,
                              void* d_out, int out_size) {
    const float* x     = (const float*)d_in[0];
    const float* w_in  = (const float*)d_in[1];
    const float* b_in  = (const float*)d_in[2];
    const float* w_out = (const float*)d_in[3];
    const float* b_out = (const float*)d_in[4];
    const float* w1    = (const float*)d_in[5];
    const float* b1    = (const float*)d_in[6];
    const float* w2    = (const float*)d_in[7];
    const float* b2    = (const float*)d_in[8];
    const float* ln1g  = (const float*)d_in[9];
    const float* ln1b  = (const float*)d_in[10];
    const float* ln2g  = (const float*)d_in[11];
    const float* ln2b  = (const float*)d_in[12];
    float* out = (float*)d_out;

    __half *xn, *kvb, *qb, *o, *hbuf, *wh;
    float *x1;
    cudaGetSymbolAddress((void**)&xn,   g_xn);
    cudaGetSymbolAddress((void**)&kvb,  g_kv);
    cudaGetSymbolAddress((void**)&qb,   g_q);
    cudaGetSymbolAddress((void**)&o,    g_o);
    cudaGetSymbolAddress((void**)&hbuf, g_h);
    cudaGetSymbolAddress((void**)&x1,   g_x1);
    cudaGetSymbolAddress((void**)&wh,   g_wh);
    __half* wh_q   = wh;                   // w_in rows 0..D   (Q)
    __half* wh_kv  = wh + (size_t)DD*DD;   // w_in rows D..3D  (K,V)
    __half* wh_out = wh + (size_t)3*1024*1024;
    __half* wh_1   = wh + (size_t)4*1024*1024;
    __half* wh_2   = wh + (size_t)8*1024*1024;

    cudaFuncSetAttribute(hgemm<0>, cudaFuncAttributeMaxDynamicSharedMemorySize, SMEM_TOT);
    cudaFuncSetAttribute(hgemm<1>, cudaFuncAttributeMaxDynamicSharedMemorySize, SMEM_TOT);
    cudaFuncSetAttribute(hgemm<2>, cudaFuncAttributeMaxDynamicSharedMemorySize, SMEM_TOT);
    cudaFuncSetAttribute(qgemm,    cudaFuncAttributeMaxDynamicSharedMemorySize, SMEM_TOT);

    // 0) convert weights to half (R10 layout: contiguous w_in | w_out | w1 | w2)
    cvt_kernel<<<(3*DD*DD/4 + 255)/256, 256>>>(w_in,  wh,     3*DD*DD/4);
    cvt_kernel<<<(DD*DD/4   + 255)/256, 256>>>(w_out, wh_out, DD*DD/4);
    cvt_kernel<<<(MLPD*DD/4 + 255)/256, 256>>>(w1,    wh_1,   MLPD*DD/4);
    cvt_kernel<<<(DD*MLPD/4 + 255)/256, 256>>>(w2,    wh_2,   DD*MLPD/4);

    // 1) LN1 -> half
    ln_kernel<<<NTOK, 256>>>(x, ln1g, ln1b, xn);
    // 2) kv = xn @ w_in[D:3D].T + b_in[D:3D]  (half; V columns fused-copied into o)
    hgemm<0><<<dim3(2*DD/128, NTOK/128), 256, SMEM_TOT>>>(
        xn, wh_kv, b_in + DD, nullptr, kvb, o, NTOK, 2*DD, DD);
    // 3) q for global rows only (gathered, standalone kernel)
    qgemm<<<dim3(DD/128, NGLOB/128), 256, SMEM_TOT>>>(xn, wh_q, b_in, qb);
    // 4) attention (overwrites global rows of o)
    attn_kernel<<<BB*HH*8, 256>>>(qb, kvb, o);
    // 5) x1 = o @ w_out.T + b_out + x  (float out)
    hgemm<1><<<dim3(DD/128, NTOK/128), 256, SMEM_TOT>>>(
        o, wh_out, b_out, x, x1, nullptr, NTOK, DD, DD);
    // 6) LN2 -> half
    ln_kernel<<<NTOK, 256>>>(x1, ln2g, ln2b, xn);
    // 7) h = gelu(xn @ w1.T + b1)  (half out)
    hgemm<2><<<dim3(MLPD/128, NTOK/128), 256, SMEM_TOT>>>(
        xn, wh_1, b1, nullptr, hbuf, nullptr, NTOK, MLPD, DD);
    // 8) out = h @ w2.T + b2 + x1  (float out)
    hgemm<1><<<dim3(DD/128, NTOK/128), 256, SMEM_TOT>>>(
        hbuf, wh_2, b2, x1, out, nullptr, NTOK, DD, MLPD);
}

// round 13
// speedup vs baseline: 1.6272x; 1.0313x over previous
#include <cuda_runtime.h>
#include <cuda_fp16.h>
#include <cstdint>

#define BB 2
#define TT 2048
#define DD 1024
#define HH 16
#define HDIM 64
#define QSTRIDE 8
#define MLPD 4096
#define NTOK (BB*TT)   // 4096
#define NGLOB (NTOK/QSTRIDE)   // 512
#define NSPLIT 4
#define NABLK (BB*HH*8*NSPLIT)  // 1024 attention blocks

// ---------------- scratch ----------------
__device__ __half g_xn[(size_t)NTOK*DD];
__device__ __half g_kv[(size_t)NTOK*2*DD];
__device__ __half g_q[(size_t)NGLOB*DD];
__device__ __half g_o[(size_t)NTOK*DD];
__device__ __half g_h[(size_t)NTOK*MLPD];
__device__ float  g_x1[(size_t)NTOK*DD];
__device__ __half g_wh[(size_t)12*1024*1024];   // w_in(3M) w_out(1M) w1(4M) w2(4M)
__device__ float  g_po[(size_t)NABLK*32*64];    // split-K partial outputs (8 MB)
__device__ float  g_pm[(size_t)NABLK*32];       // partial max
__device__ float  g_pl[(size_t)NABLK*32];       // partial sum

// ---------------- helpers ----------------
__device__ __forceinline__ uint32_t smem_u32(const void* p) {
    uint32_t a;
    asm("{ .reg .u64 t; cvta.to.shared.u64 t, %1; cvt.u32.u64 %0, t; }" : "=r"(a) : "l"(p));
    return a;
}
#define CP_ASYNC16(dst, src) \
    asm volatile("cp.async.cg.shared.global [%0], [%1], 16;" :: "r"(dst), "l"(src) : "memory")
#define CP_COMMIT() asm volatile("cp.async.commit_group;" ::: "memory")
#define CP_WAIT0() asm volatile("cp.async.wait_group 0;" ::: "memory")
#define CP_WAIT1() asm volatile("cp.async.wait_group 1;" ::: "memory")

#define LDSM_X4(r0, r1, r2, r3, addr) \
    asm volatile("ldmatrix.sync.aligned.m8n8.x4.shared.b16 {%0,%1,%2,%3}, [%4];" \
        : "=r"(r0), "=r"(r1), "=r"(r2), "=r"(r3) : "r"(addr))

__device__ __forceinline__ void mma_f16(float* d, const uint32_t* a, const uint32_t* b) {
    asm volatile(
        "mma.sync.aligned.m16n8k16.row.col.f32.f16.f16.f32 "
        "{%0,%1,%2,%3}, {%4,%5,%6,%7}, {%8,%9}, {%0,%1,%2,%3};"
        : "+f"(d[0]), "+f"(d[1]), "+f"(d[2]), "+f"(d[3])
        : "r"(a[0]), "r"(a[1]), "r"(a[2]), "r"(a[3]), "r"(b[0]), "r"(b[1]));
}

// ---------------- fp16 mma GEMM (R10 codegen): C = A @ W.T + bias (+epi) -------
#define ROWH 72
#define STG_B (128*ROWH*2)
#define STAGE_B (2*STG_B)
#define NSTG 3
#define SMEM_TOT (NSTG*STAGE_B)         // 110592 B -> 2 CTAs/SM

template <int EPI>  // 0=bias->half(+opt vout for c>=DD), 1=bias+residual->float, 2=bias+GELU->half
__global__ void __launch_bounds__(256, 2)
hgemm(const __half* __restrict__ A, const __half* __restrict__ W,
      const float* __restrict__ bias, const float* __restrict__ res,
      void* __restrict__ Cv, __half* __restrict__ vout, int M, int N, int K)
{
    extern __shared__ __half smem[];
    uint32_t sbase = smem_u32(smem);
    int tid = threadIdx.x;
    int wid = tid >> 5, lane = tid & 31;
    int gp = lane >> 2, tc = lane & 3;
    int m0 = blockIdx.y * 128, n0 = blockIdx.x * 128;
    int wm = (wid & 1) * 64;
    int wn = (wid >> 1) * 32;

    int a_row = lane & 15;
    int a_k8  = (lane >> 4) * 8;
    int b_grp = lane >> 3;
    int b_row = lane & 7;
    int b_nof = (b_grp >> 1) * 8 + b_row;
    int b_k8  = (b_grp & 1) * 8;

    float acc[4][4][4];
    #pragma unroll
    for (int i = 0; i < 4; i++)
        #pragma unroll
        for (int j = 0; j < 4; j++)
            #pragma unroll
            for (int k = 0; k < 4; k++) acc[i][j][k] = 0.f;

    const int KT = K >> 6;

    auto load_tile = [&](int s, int kt) {
        uint32_t sa = sbase + s * STAGE_B;
        uint32_t sb = sa + STG_B;
        const __half* Ag = A + (size_t)m0 * K + kt * 64;
        const __half* Wg = W + (size_t)n0 * K + kt * 64;
        #pragma unroll
        for (int i = 0; i < 4; i++) {
            int idx = i * 256 + tid;
            int row = idx >> 3, ch = idx & 7;
            CP_ASYNC16(sa + (row * ROWH + ch * 8) * 2, Ag + (size_t)row * K + ch * 8);
        }
        #pragma unroll
        for (int i = 0; i < 4; i++) {
            int idx = i * 256 + tid;
            int row = idx >> 3, ch = idx & 7;
            CP_ASYNC16(sb + (row * ROWH + ch * 8) * 2, Wg + (size_t)row * K + ch * 8);
        }
        CP_COMMIT();
    };

    load_tile(0, 0);
    load_tile(1, 1);

    for (int kt = 0; kt < KT; kt++) {
        if (kt + 1 < KT) { CP_WAIT1(); } else { CP_WAIT0(); }
        __syncthreads();
        if (kt + 2 < KT) load_tile((kt + 2) % NSTG, kt + 2);

        uint32_t sa = sbase + (kt % NSTG) * STAGE_B;
        uint32_t sb = sa + STG_B;

        #pragma unroll
        for (int ks = 0; ks < 4; ks++) {
            uint32_t af[4][4], bf[2][4];
            #pragma unroll
            for (int mt = 0; mt < 4; mt++)
                LDSM_X4(af[mt][0], af[mt][1], af[mt][2], af[mt][3],
                        sa + ((wm + mt * 16 + a_row) * ROWH + ks * 16 + a_k8) * 2);
            #pragma unroll
            for (int p = 0; p < 2; p++)
                LDSM_X4(bf[p][0], bf[p][1], bf[p][2], bf[p][3],
                        sb + ((wn + p * 16 + b_nof) * ROWH + ks * 16 + b_k8) * 2);
            #pragma unroll
            for (int mt = 0; mt < 4; mt++)
                #pragma unroll
                for (int nt = 0; nt < 4; nt++)
                    mma_f16(acc[mt][nt], af[mt], &bf[nt >> 1][(nt & 1) * 2]);
        }
    }

    #pragma unroll
    for (int mt = 0; mt < 4; mt++) {
        int r0 = m0 + wm + mt * 16 + gp;
        #pragma unroll
        for (int nt = 0; nt < 4; nt++) {
            int c = n0 + wn + nt * 8 + 2 * tc;
            float bx = bias[c], by = bias[c + 1];
            #pragma unroll
            for (int half_ = 0; half_ < 2; half_++) {
                int r = r0 + half_ * 8;
                float vx = acc[mt][nt][half_ * 2 + 0] + bx;
                float vy = acc[mt][nt][half_ * 2 + 1] + by;
                size_t off = (size_t)r * N + c;
                if (EPI == 1) {
                    float2 rr = *(const float2*)(res + off);
                    vx += rr.x; vy += rr.y;
                    float2 o2; o2.x = vx; o2.y = vy;
                    *(float2*)((float*)Cv + off) = o2;
                } else {
                    if (EPI == 2) {
                        vx = 0.5f * vx * (1.0f + erff(vx * 0.70710678118f));
                        vy = 0.5f * vy * (1.0f + erff(vy * 0.70710678118f));
                    }
                    __half2 hv = __floats2half2_rn(vx, vy);
                    *(__half2*)((__half*)Cv + off) = hv;
                    if (EPI == 0 && vout != nullptr && c >= DD) {
                        *(__half2*)(vout + (size_t)r * DD + (c - DD)) = hv;
                    }
                }
            }
        }
    }
}

// ---------------- standalone Q GEMM: qb[g] = xn[8g] @ Wq.T + bq ---------------
__global__ void __launch_bounds__(256, 2)
qgemm(const __half* __restrict__ A, const __half* __restrict__ W,
      const float* __restrict__ bias, __half* __restrict__ C)
{
    extern __shared__ __half smem[];
    uint32_t sbase = smem_u32(smem);
    const int K = DD, N = DD;
    int tid = threadIdx.x;
    int wid = tid >> 5, lane = tid & 31;
    int gp = lane >> 2, tc = lane & 3;
    int m0 = blockIdx.y * 128, n0 = blockIdx.x * 128;
    int wm = (wid & 1) * 64;
    int wn = (wid >> 1) * 32;

    int a_row = lane & 15;
    int a_k8  = (lane >> 4) * 8;
    int b_grp = lane >> 3;
    int b_row = lane & 7;
    int b_nof = (b_grp >> 1) * 8 + b_row;
    int b_k8  = (b_grp & 1) * 8;

    float acc[4][4][4];
    #pragma unroll
    for (int i = 0; i < 4; i++)
        #pragma unroll
        for (int j = 0; j < 4; j++)
            #pragma unroll
            for (int k = 0; k < 4; k++) acc[i][j][k] = 0.f;

    const int KT = K >> 6;

    auto load_tile = [&](int s, int kt) {
        uint32_t sa = sbase + s * STAGE_B;
        uint32_t sb = sa + STG_B;
        const __half* Ag = A + kt * 64;
        const __half* Wg = W + (size_t)n0 * K + kt * 64;
        #pragma unroll
        for (int i = 0; i < 4; i++) {
            int idx = i * 256 + tid;
            int row = idx >> 3, ch = idx & 7;
            CP_ASYNC16(sa + (row * ROWH + ch * 8) * 2,
                       Ag + (size_t)(m0 + row) * (QSTRIDE * DD) + ch * 8);
        }
        #pragma unroll
        for (int i = 0; i < 4; i++) {
            int idx = i * 256 + tid;
            int row = idx >> 3, ch = idx & 7;
            CP_ASYNC16(sb + (row * ROWH + ch * 8) * 2, Wg + (size_t)row * K + ch * 8);
        }
        CP_COMMIT();
    };

    load_tile(0, 0);
    load_tile(1, 1);

    for (int kt = 0; kt < KT; kt++) {
        if (kt + 1 < KT) { CP_WAIT1(); } else { CP_WAIT0(); }
        __syncthreads();
        if (kt + 2 < KT) load_tile((kt + 2) % NSTG, kt + 2);

        uint32_t sa = sbase + (kt % NSTG) * STAGE_B;
        uint32_t sb = sa + STG_B;

        #pragma unroll
        for (int ks = 0; ks < 4; ks++) {
            uint32_t af[4][4], bf[2][4];
            #pragma unroll
            for (int mt = 0; mt < 4; mt++)
                LDSM_X4(af[mt][0], af[mt][1], af[mt][2], af[mt][3],
                        sa + ((wm + mt * 16 + a_row) * ROWH + ks * 16 + a_k8) * 2);
            #pragma unroll
            for (int p = 0; p < 2; p++)
                LDSM_X4(bf[p][0], bf[p][1], bf[p][2], bf[p][3],
                        sb + ((wn + p * 16 + b_nof) * ROWH + ks * 16 + b_k8) * 2);
            #pragma unroll
            for (int mt = 0; mt < 4; mt++)
                #pragma unroll
                for (int nt = 0; nt < 4; nt++)
                    mma_f16(acc[mt][nt], af[mt], &bf[nt >> 1][(nt & 1) * 2]);
        }
    }

    #pragma unroll
    for (int mt = 0; mt < 4; mt++) {
        int r0 = m0 + wm + mt * 16 + gp;
        #pragma unroll
        for (int nt = 0; nt < 4; nt++) {
            int c = n0 + wn + nt * 8 + 2 * tc;
            float bx = bias[c], by = bias[c + 1];
            #pragma unroll
            for (int half_ = 0; half_ < 2; half_++) {
                int r = r0 + half_ * 8;
                float vx = acc[mt][nt][half_ * 2 + 0] + bx;
                float vy = acc[mt][nt][half_ * 2 + 1] + by;
                *(__half2*)(C + (size_t)r * N + c) = __floats2half2_rn(vx, vy);
            }
        }
    }
}

// ---------------- LayerNorm (float in, half out) ----------------
__global__ void ln_kernel(const float* __restrict__ x, const float* __restrict__ g,
                          const float* __restrict__ b, __half* __restrict__ out) {
    int row = blockIdx.x;
    int tid = threadIdx.x;
    const float4* xr = (const float4*)(x + (size_t)row * DD);
    float4 v = xr[tid];
    float s  = v.x + v.y + v.z + v.w;
    float ss = v.x*v.x + v.y*v.y + v.z*v.z + v.w*v.w;
    #pragma unroll
    for (int o = 16; o; o >>= 1) {
        s  += __shfl_xor_sync(0xffffffffu, s,  o);
        ss += __shfl_xor_sync(0xffffffffu, ss, o);
    }
    __shared__ float sm[8], sm2[8];
    int w = tid >> 5, l = tid & 31;
    if (l == 0) { sm[w] = s; sm2[w] = ss; }
    __syncthreads();
    float tot = 0.f, tot2 = 0.f;
    #pragma unroll
    for (int i = 0; i < 8; i++) { tot += sm[i]; tot2 += sm2[i]; }
    float mean = tot * (1.0f / DD);
    float var  = tot2 * (1.0f / DD) - mean * mean;
    float rstd = rsqrtf(var + 1e-5f);
    float4 gg = ((const float4*)g)[tid];
    float4 bb = ((const float4*)b)[tid];
    __half2 h0 = __floats2half2_rn((v.x - mean) * rstd * gg.x + bb.x,
                                   (v.y - mean) * rstd * gg.y + bb.y);
    __half2 h1 = __floats2half2_rn((v.z - mean) * rstd * gg.z + bb.z,
                                   (v.w - mean) * rstd * gg.w + bb.w);
    uint2 u;
    u.x = *(uint32_t*)&h0; u.y = *(uint32_t*)&h1;
    ((uint2*)(out + (size_t)row * DD))[tid] = u;
}

// ---------------- convert ALL weights float -> half (one kernel) ----------------
#define CVT_N0 786432
#define CVT_N1 (CVT_N0 + 262144)
#define CVT_N2 (CVT_N1 + 1048576)
#define CVT_N3 (CVT_N2 + 1048576)
__global__ void cvt_all_kernel(const float* __restrict__ w_in, const float* __restrict__ w_out,
                               const float* __restrict__ w1, const float* __restrict__ w2,
                               __half* __restrict__ oh) {
    int i = blockIdx.x * blockDim.x + threadIdx.x;
    if (i >= CVT_N3) return;
    const float* src; int j;
    if (i < CVT_N0)      { src = w_in;  j = i; }
    else if (i < CVT_N1) { src = w_out; j = i - CVT_N0; }
    else if (i < CVT_N2) { src = w1;    j = i - CVT_N1; }
    else                 { src = w2;    j = i - CVT_N2; }
    float4 v = ((const float4*)src)[j];
    __half2 h0 = __floats2half2_rn(v.x, v.y);
    __half2 h1 = __floats2half2_rn(v.z, v.w);
    uint2 u; u.x = *(uint32_t*)&h0; u.y = *(uint32_t*)&h1;
    ((uint2*)oh)[i] = u;
}

// ---------------- split-K attention: each block handles 512 keys --------------
// grid = 1024: bid = b*512 + h*32 + qt*4 + s
__global__ void __launch_bounds__(256)
attn_part_kernel(const __half* __restrict__ qbuf, const __half* __restrict__ kv,
                 float* __restrict__ po, float* __restrict__ pm, float* __restrict__ pl) {
    int bid = blockIdx.x;
    int s  = bid & 3;
    int qt = (bid >> 2) & 7;
    int h  = (bid >> 5) & 15;
    int b  = bid >> 9;

    __shared__ float Qs[32][68];
    __shared__ float Ks[32][68];
    __shared__ float Vs[32][68];
    __shared__ float S [32][36];

    int tid = threadIdx.x;
    int qi_ = tid >> 3, d8 = tid & 7;

    {
        int g = b * 256 + qt * 32 + qi_;
        uint4 u = *(const uint4*)(qbuf + (size_t)g * DD + h * HDIM + d8 * 8);
        const __half2* hp = (const __half2*)&u;
        #pragma unroll
        for (int j = 0; j < 4; j++) {
            float2 f = __half22float2(hp[j]);
            Qs[qi_][d8 * 8 + j * 2]     = f.x * 0.125f;
            Qs[qi_][d8 * 8 + j * 2 + 1] = f.y * 0.125f;
        }
    }
    __syncthreads();

    int qi = tid >> 3, sl = tid & 7;
    float mrun = -1e30f, lrun = 0.f;
    float oacc[8] = {};

    for (int kt = s * 16; kt < s * 16 + 16; kt++) {
        {
            size_t base = (size_t)(b * TT + kt * 32 + qi_) * (2 * DD) + h * HDIM + d8 * 8;
            uint4 uk = *(const uint4*)(kv + base);
            uint4 uv = *(const uint4*)(kv + base + DD);
            const __half2* kp = (const __half2*)&uk;
            const __half2* vp = (const __half2*)&uv;
            #pragma unroll
            for (int j = 0; j < 4; j++) {
                float2 fk = __half22float2(kp[j]);
                float2 fv = __half22float2(vp[j]);
                Ks[qi_][d8 * 8 + j * 2] = fk.x;  Ks[qi_][d8 * 8 + j * 2 + 1] = fk.y;
                Vs[qi_][d8 * 8 + j * 2] = fv.x;  Vs[qi_][d8 * 8 + j * 2 + 1] = fv.y;
            }
        }
        __syncthreads();

        float s4[4] = {0.f, 0.f, 0.f, 0.f};
        #pragma unroll
        for (int d4 = 0; d4 < 16; d4++) {
            float4 qv = *(const float4*)&Qs[qi][d4 * 4];
            #pragma unroll
            for (int kj = 0; kj < 4; kj++) {
                float4 kvv = *(const float4*)&Ks[kj * 8 + sl][d4 * 4];
                s4[kj] += qv.x * kvv.x + qv.y * kvv.y + qv.z * kvv.z + qv.w * kvv.w;
            }
        }
        float tmax = fmaxf(fmaxf(s4[0], s4[1]), fmaxf(s4[2], s4[3]));
        #pragma unroll
        for (int off = 4; off; off >>= 1)
            tmax = fmaxf(tmax, __shfl_xor_sync(0xffffffffu, tmax, off));
        float mnew = fmaxf(mrun, tmax);
        float psum = 0.f;
        #pragma unroll
        for (int kj = 0; kj < 4; kj++) {
            float p = __expf(s4[kj] - mnew);
            psum += p;
            S[qi][kj * 8 + sl] = p;
        }
        #pragma unroll
        for (int off = 4; off; off >>= 1)
            psum += __shfl_xor_sync(0xffffffffu, psum, off);
        float factor = __expf(mrun - mnew);
        lrun = lrun * factor + psum;
        mrun = mnew;
        __syncwarp();

        #pragma unroll
        for (int j = 0; j < 8; j++) oacc[j] *= factor;
        #pragma unroll
        for (int key = 0; key < 32; key++) {
            float p = S[qi][key];
            float4 v0 = *(const float4*)&Vs[key][sl * 8];
            float4 v1 = *(const float4*)&Vs[key][sl * 8 + 4];
            oacc[0] += p * v0.x; oacc[1] += p * v0.y;
            oacc[2] += p * v0.z; oacc[3] += p * v0.w;
            oacc[4] += p * v1.x; oacc[5] += p * v1.y;
            oacc[6] += p * v1.z; oacc[7] += p * v1.w;
        }
        __syncthreads();
    }

    // write unnormalized partials
    float* pop = po + (size_t)bid * 2048 + qi * 64 + sl * 8;
    *(float4*)pop       = make_float4(oacc[0], oacc[1], oacc[2], oacc[3]);
    *(float4*)(pop + 4) = make_float4(oacc[4], oacc[5], oacc[6], oacc[7]);
    if (sl == 0) {
        pm[bid * 32 + qi] = mrun;
        pl[bid * 32 + qi] = lrun;
    }
}

// ---------------- combine 4 split partials -> o (half) ----------------
// 65536 threads: g = b*32768 + h*2048 + qt*256 + qi*8 + d8
__global__ void attn_combine_kernel(const float* __restrict__ po, const float* __restrict__ pm,
                                    const float* __restrict__ pl, __half* __restrict__ o) {
    int g = blockIdx.x * blockDim.x + threadIdx.x;
    int d8 = g & 7;
    int qi = (g >> 3) & 31;
    int qt = (g >> 8) & 7;
    int h  = (g >> 11) & 15;
    int b  = g >> 15;

    int bid0 = b * 512 + h * 32 + qt * 4;
    float m0 = pm[(bid0 + 0) * 32 + qi], m1 = pm[(bid0 + 1) * 32 + qi];
    float m2 = pm[(bid0 + 2) * 32 + qi], m3 = pm[(bid0 + 3) * 32 + qi];
    float mm = fmaxf(fmaxf(m0, m1), fmaxf(m2, m3));
    float e0 = __expf(m0 - mm), e1 = __expf(m1 - mm);
    float e2 = __expf(m2 - mm), e3 = __expf(m3 - mm);
    float denom = e0 * pl[(bid0 + 0) * 32 + qi] + e1 * pl[(bid0 + 1) * 32 + qi]
                + e2 * pl[(bid0 + 2) * 32 + qi] + e3 * pl[(bid0 + 3) * 32 + qi];
    float inv = 1.0f / denom;

    const float* p0 = po + (size_t)(bid0 + 0) * 2048 + qi * 64 + d8 * 8;
    const float* p1 = po + (size_t)(bid0 + 1) * 2048 + qi * 64 + d8 * 8;
    const float* p2 = po + (size_t)(bid0 + 2) * 2048 + qi * 64 + d8 * 8;
    const float* p3 = po + (size_t)(bid0 + 3) * 2048 + qi * 64 + d8 * 8;

    float res[8];
    #pragma unroll
    for (int j = 0; j < 8; j++)
        res[j] = (e0 * p0[j] + e1 * p1[j] + e2 * p2[j] + e3 * p3[j]) * inv;

    int t = (qt * 32 + qi) * QSTRIDE;
    __half2 h0 = __floats2half2_rn(res[0], res[1]);
    __half2 h1 = __floats2half2_rn(res[2], res[3]);
    __half2 h2 = __floats2half2_rn(res[4], res[5]);
    __half2 h3 = __floats2half2_rn(res[6], res[7]);
    uint4 u;
    u.x = *(uint32_t*)&h0; u.y = *(uint32_t*)&h1;
    u.z = *(uint32_t*)&h2; u.w = *(uint32_t*)&h3;
    *(uint4*)(o + (size_t)(b * TT + t) * DD + h * HDIM + d8 * 8) = u;
}

// ---------------- launch ----------------
extern "C" void kernel_launch(void* const* d_in, const int* in_sizes, int n_in,
                              void* d_out, int out_size) {
    const float* x     = (const float*)d_in[0];
    const float* w_in  = (const float*)d_in[1];
    const float* b_in  = (const float*)d_in[2];
    const float* w_out = (const float*)d_in[3];
    const float* b_out = (const float*)d_in[4];
    const float* w1    = (const float*)d_in[5];
    const float* b1    = (const float*)d_in[6];
    const float* w2    = (const float*)d_in[7];
    const float* b2    = (const float*)d_in[8];
    const float* ln1g  = (const float*)d_in[9];
    const float* ln1b  = (const float*)d_in[10];
    const float* ln2g  = (const float*)d_in[11];
    const float* ln2b  = (const float*)d_in[12];
    float* out = (float*)d_out;

    __half *xn, *kvb, *qb, *o, *hbuf, *wh;
    float *x1, *po, *pm, *pl;
    cudaGetSymbolAddress((void**)&xn,   g_xn);
    cudaGetSymbolAddress((void**)&kvb,  g_kv);
    cudaGetSymbolAddress((void**)&qb,   g_q);
    cudaGetSymbolAddress((void**)&o,    g_o);
    cudaGetSymbolAddress((void**)&hbuf, g_h);
    cudaGetSymbolAddress((void**)&x1,   g_x1);
    cudaGetSymbolAddress((void**)&wh,   g_wh);
    cudaGetSymbolAddress((void**)&po,   g_po);
    cudaGetSymbolAddress((void**)&pm,   g_pm);
    cudaGetSymbolAddress((void**)&pl,   g_pl);
    __half* wh_q   = wh;
    __half* wh_kv  = wh + (size_t)DD*DD;
    __half* wh_out = wh + (size_t)3*1024*1024;
    __half* wh_1   = wh + (size_t)4*1024*1024;
    __half* wh_2   = wh + (size_t)8*1024*1024;

    cudaFuncSetAttribute(hgemm<0>, cudaFuncAttributeMaxDynamicSharedMemorySize, SMEM_TOT);
    cudaFuncSetAttribute(hgemm<1>, cudaFuncAttributeMaxDynamicSharedMemorySize, SMEM_TOT);
    cudaFuncSetAttribute(hgemm<2>, cudaFuncAttributeMaxDynamicSharedMemorySize, SMEM_TOT);
    cudaFuncSetAttribute(qgemm,    cudaFuncAttributeMaxDynamicSharedMemorySize, SMEM_TOT);

    // 0) convert all weights to half (single kernel)
    cvt_all_kernel<<<(CVT_N3 + 255)/256, 256>>>(w_in, w_out, w1, w2, wh);
    // 1) LN1 -> half
    ln_kernel<<<NTOK, 256>>>(x, ln1g, ln1b, xn);
    // 2) kv = xn @ w_in[D:3D].T + b_in[D:3D]  (half; V columns fused-copied into o)
    hgemm<0><<<dim3(2*DD/128, NTOK/128), 256, SMEM_TOT>>>(
        xn, wh_kv, b_in + DD, nullptr, kvb, o, NTOK, 2*DD, DD);
    // 3) q for global rows only (gathered, standalone kernel)
    qgemm<<<dim3(DD/128, NGLOB/128), 256, SMEM_TOT>>>(xn, wh_q, b_in, qb);
    // 4) split-K attention partials + combine (overwrites global rows of o)
    attn_part_kernel<<<NABLK, 256>>>(qb, kvb, po, pm, pl);
    attn_combine_kernel<<<65536/256, 256>>>(po, pm, pl, o);
    // 5) x1 = o @ w_out.T + b_out + x  (float out)
    hgemm<1><<<dim3(DD/128, NTOK/128), 256, SMEM_TOT>>>(
        o, wh_out, b_out, x, x1, nullptr, NTOK, DD, DD);
    // 6) LN2 -> half
    ln_kernel<<<NTOK, 256>>>(x1, ln2g, ln2b, xn);
    // 7) h = gelu(xn @ w1.T + b1)  (half out)
    hgemm<2><<<dim3(MLPD/128, NTOK/128), 256, SMEM_TOT>>>(
        xn, wh_1, b1, nullptr, hbuf, nullptr, NTOK, MLPD, DD);
    // 8) out = h @ w2.T + b2 + x1  (float out)
    hgemm<1><<<dim3(DD/128, NTOK/128), 256, SMEM_TOT>>>(
        hbuf, wh_2, b2, x1, out, nullptr, NTOK, DD, MLPD);
}

// round 15
// speedup vs baseline: 1.7387x; 1.0685x over previous
#include <cuda_runtime.h>
#include <cuda_fp16.h>
#include <cstdint>

#define BB 2
#define TT 2048
#define DD 1024
#define HH 16
#define HDIM 64
#define QSTRIDE 8
#define MLPD 4096
#define NTOK (BB*TT)   // 4096
#define NGLOB (NTOK/QSTRIDE)   // 512
#define NSPLIT 4
#define NABLK (BB*HH*8*NSPLIT)  // 1024 attention blocks

// ---------------- scratch ----------------
__device__ __half g_xn[(size_t)NTOK*DD];
__device__ __half g_kv[(size_t)NTOK*2*DD];
__device__ __half g_q[(size_t)NGLOB*DD];
__device__ __half g_o[(size_t)NTOK*DD];
__device__ __half g_h[(size_t)NTOK*MLPD];
__device__ float  g_x1[(size_t)NTOK*DD];
__device__ __half g_wh[(size_t)12*1024*1024];   // w_in(3M) w_out(1M) w1(4M) w2(4M)
__device__ float  g_po[(size_t)NABLK*32*64];    // split-K partial outputs (8 MB)
__device__ float  g_pm[(size_t)NABLK*32];       // partial max
__device__ float  g_pl[(size_t)NABLK*32];       // partial sum

// ---------------- helpers ----------------
__device__ __forceinline__ uint32_t smem_u32(const void* p) {
    uint32_t a;
    asm("{ .reg .u64 t; cvta.to.shared.u64 t, %1; cvt.u32.u64 %0, t; }" : "=r"(a) : "l"(p));
    return a;
}
#define CP_ASYNC16(dst, src) \
    asm volatile("cp.async.cg.shared.global [%0], [%1], 16;" :: "r"(dst), "l"(src) : "memory")
#define CP_COMMIT() asm volatile("cp.async.commit_group;" ::: "memory")
#define CP_WAIT0() asm volatile("cp.async.wait_group 0;" ::: "memory")
#define CP_WAIT1() asm volatile("cp.async.wait_group 1;" ::: "memory")

#define LDSM_X4(r0, r1, r2, r3, addr) \
    asm volatile("ldmatrix.sync.aligned.m8n8.x4.shared.b16 {%0,%1,%2,%3}, [%4];" \
        : "=r"(r0), "=r"(r1), "=r"(r2), "=r"(r3) : "r"(addr))

__device__ __forceinline__ void mma_f16(float* d, const uint32_t* a, const uint32_t* b) {
    asm volatile(
        "mma.sync.aligned.m16n8k16.row.col.f32.f16.f16.f32 "
        "{%0,%1,%2,%3}, {%4,%5,%6,%7}, {%8,%9}, {%0,%1,%2,%3};"
        : "+f"(d[0]), "+f"(d[1]), "+f"(d[2]), "+f"(d[3])
        : "r"(a[0]), "r"(a[1]), "r"(a[2]), "r"(a[3]), "r"(b[0]), "r"(b[1]));
}

// ---------------- fp16 mma GEMM (R10 codegen): C = A @ W.T + bias (+epi) -------
#define ROWH 72
#define STG_B (128*ROWH*2)
#define STAGE_B (2*STG_B)
#define NSTG 3
#define SMEM_TOT (NSTG*STAGE_B)         // 110592 B -> 2 CTAs/SM

template <int EPI>  // 0=bias->half(+opt vout for c>=DD), 1=bias+residual->float, 2=bias+GELU->half
__global__ void __launch_bounds__(256, 2)
hgemm(const __half* __restrict__ A, const __half* __restrict__ W,
      const float* __restrict__ bias, const float* __restrict__ res,
      void* __restrict__ Cv, __half* __restrict__ vout, int M, int N, int K)
{
    extern __shared__ __half smem[];
    uint32_t sbase = smem_u32(smem);
    int tid = threadIdx.x;
    int wid = tid >> 5, lane = tid & 31;
    int gp = lane >> 2, tc = lane & 3;
    int m0 = blockIdx.y * 128, n0 = blockIdx.x * 128;
    int wm = (wid & 1) * 64;
    int wn = (wid >> 1) * 32;

    int a_row = lane & 15;
    int a_k8  = (lane >> 4) * 8;
    int b_grp = lane >> 3;
    int b_row = lane & 7;
    int b_nof = (b_grp >> 1) * 8 + b_row;
    int b_k8  = (b_grp & 1) * 8;

    float acc[4][4][4];
    #pragma unroll
    for (int i = 0; i < 4; i++)
        #pragma unroll
        for (int j = 0; j < 4; j++)
            #pragma unroll
            for (int k = 0; k < 4; k++) acc[i][j][k] = 0.f;

    const int KT = K >> 6;

    auto load_tile = [&](int s, int kt) {
        uint32_t sa = sbase + s * STAGE_B;
        uint32_t sb = sa + STG_B;
        const __half* Ag = A + (size_t)m0 * K + kt * 64;
        const __half* Wg = W + (size_t)n0 * K + kt * 64;
        #pragma unroll
        for (int i = 0; i < 4; i++) {
            int idx = i * 256 + tid;
            int row = idx >> 3, ch = idx & 7;
            CP_ASYNC16(sa + (row * ROWH + ch * 8) * 2, Ag + (size_t)row * K + ch * 8);
        }
        #pragma unroll
        for (int i = 0; i < 4; i++) {
            int idx = i * 256 + tid;
            int row = idx >> 3, ch = idx & 7;
            CP_ASYNC16(sb + (row * ROWH + ch * 8) * 2, Wg + (size_t)row * K + ch * 8);
        }
        CP_COMMIT();
    };

    load_tile(0, 0);
    load_tile(1, 1);

    for (int kt = 0; kt < KT; kt++) {
        if (kt + 1 < KT) { CP_WAIT1(); } else { CP_WAIT0(); }
        __syncthreads();
        if (kt + 2 < KT) load_tile((kt + 2) % NSTG, kt + 2);

        uint32_t sa = sbase + (kt % NSTG) * STAGE_B;
        uint32_t sb = sa + STG_B;

        #pragma unroll
        for (int ks = 0; ks < 4; ks++) {
            uint32_t af[4][4], bf[2][4];
            #pragma unroll
            for (int mt = 0; mt < 4; mt++)
                LDSM_X4(af[mt][0], af[mt][1], af[mt][2], af[mt][3],
                        sa + ((wm + mt * 16 + a_row) * ROWH + ks * 16 + a_k8) * 2);
            #pragma unroll
            for (int p = 0; p < 2; p++)
                LDSM_X4(bf[p][0], bf[p][1], bf[p][2], bf[p][3],
                        sb + ((wn + p * 16 + b_nof) * ROWH + ks * 16 + b_k8) * 2);
            #pragma unroll
            for (int mt = 0; mt < 4; mt++)
                #pragma unroll
                for (int nt = 0; nt < 4; nt++)
                    mma_f16(acc[mt][nt], af[mt], &bf[nt >> 1][(nt & 1) * 2]);
        }
    }

    #pragma unroll
    for (int mt = 0; mt < 4; mt++) {
        int r0 = m0 + wm + mt * 16 + gp;
        #pragma unroll
        for (int nt = 0; nt < 4; nt++) {
            int c = n0 + wn + nt * 8 + 2 * tc;
            float bx = bias[c], by = bias[c + 1];
            #pragma unroll
            for (int half_ = 0; half_ < 2; half_++) {
                int r = r0 + half_ * 8;
                float vx = acc[mt][nt][half_ * 2 + 0] + bx;
                float vy = acc[mt][nt][half_ * 2 + 1] + by;
                size_t off = (size_t)r * N + c;
                if (EPI == 1) {
                    float2 rr = *(const float2*)(res + off);
                    vx += rr.x; vy += rr.y;
                    float2 o2; o2.x = vx; o2.y = vy;
                    *(float2*)((float*)Cv + off) = o2;
                } else {
                    if (EPI == 2) {
                        vx = 0.5f * vx * (1.0f + erff(vx * 0.70710678118f));
                        vy = 0.5f * vy * (1.0f + erff(vy * 0.70710678118f));
                    }
                    __half2 hv = __floats2half2_rn(vx, vy);
                    *(__half2*)((__half*)Cv + off) = hv;
                    if (EPI == 0 && vout != nullptr && c >= DD) {
                        *(__half2*)(vout + (size_t)r * DD + (c - DD)) = hv;
                    }
                }
            }
        }
    }
}

// ---------------- standalone Q GEMM: qb[g] = xn[8g] @ Wq.T + bq ---------------
__global__ void __launch_bounds__(256, 2)
qgemm(const __half* __restrict__ A, const __half* __restrict__ W,
      const float* __restrict__ bias, __half* __restrict__ C)
{
    extern __shared__ __half smem[];
    uint32_t sbase = smem_u32(smem);
    const int K = DD, N = DD;
    int tid = threadIdx.x;
    int wid = tid >> 5, lane = tid & 31;
    int gp = lane >> 2, tc = lane & 3;
    int m0 = blockIdx.y * 128, n0 = blockIdx.x * 128;
    int wm = (wid & 1) * 64;
    int wn = (wid >> 1) * 32;

    int a_row = lane & 15;
    int a_k8  = (lane >> 4) * 8;
    int b_grp = lane >> 3;
    int b_row = lane & 7;
    int b_nof = (b_grp >> 1) * 8 + b_row;
    int b_k8  = (b_grp & 1) * 8;

    float acc[4][4][4];
    #pragma unroll
    for (int i = 0; i < 4; i++)
        #pragma unroll
        for (int j = 0; j < 4; j++)
            #pragma unroll
            for (int k = 0; k < 4; k++) acc[i][j][k] = 0.f;

    const int KT = K >> 6;

    auto load_tile = [&](int s, int kt) {
        uint32_t sa = sbase + s * STAGE_B;
        uint32_t sb = sa + STG_B;
        const __half* Ag = A + kt * 64;
        const __half* Wg = W + (size_t)n0 * K + kt * 64;
        #pragma unroll
        for (int i = 0; i < 4; i++) {
            int idx = i * 256 + tid;
            int row = idx >> 3, ch = idx & 7;
            CP_ASYNC16(sa + (row * ROWH + ch * 8) * 2,
                       Ag + (size_t)(m0 + row) * (QSTRIDE * DD) + ch * 8);
        }
        #pragma unroll
        for (int i = 0; i < 4; i++) {
            int idx = i * 256 + tid;
            int row = idx >> 3, ch = idx & 7;
            CP_ASYNC16(sb + (row * ROWH + ch * 8) * 2, Wg + (size_t)row * K + ch * 8);
        }
        CP_COMMIT();
    };

    load_tile(0, 0);
    load_tile(1, 1);

    for (int kt = 0; kt < KT; kt++) {
        if (kt + 1 < KT) { CP_WAIT1(); } else { CP_WAIT0(); }
        __syncthreads();
        if (kt + 2 < KT) load_tile((kt + 2) % NSTG, kt + 2);

        uint32_t sa = sbase + (kt % NSTG) * STAGE_B;
        uint32_t sb = sa + STG_B;

        #pragma unroll
        for (int ks = 0; ks < 4; ks++) {
            uint32_t af[4][4], bf[2][4];
            #pragma unroll
            for (int mt = 0; mt < 4; mt++)
                LDSM_X4(af[mt][0], af[mt][1], af[mt][2], af[mt][3],
                        sa + ((wm + mt * 16 + a_row) * ROWH + ks * 16 + a_k8) * 2);
            #pragma unroll
            for (int p = 0; p < 2; p++)
                LDSM_X4(bf[p][0], bf[p][1], bf[p][2], bf[p][3],
                        sb + ((wn + p * 16 + b_nof) * ROWH + ks * 16 + b_k8) * 2);
            #pragma unroll
            for (int mt = 0; mt < 4; mt++)
                #pragma unroll
                for (int nt = 0; nt < 4; nt++)
                    mma_f16(acc[mt][nt], af[mt], &bf[nt >> 1][(nt & 1) * 2]);
        }
    }

    #pragma unroll
    for (int mt = 0; mt < 4; mt++) {
        int r0 = m0 + wm + mt * 16 + gp;
        #pragma unroll
        for (int nt = 0; nt < 4; nt++) {
            int c = n0 + wn + nt * 8 + 2 * tc;
            float bx = bias[c], by = bias[c + 1];
            #pragma unroll
            for (int half_ = 0; half_ < 2; half_++) {
                int r = r0 + half_ * 8;
                float vx = acc[mt][nt][half_ * 2 + 0] + bx;
                float vy = acc[mt][nt][half_ * 2 + 1] + by;
                *(__half2*)(C + (size_t)r * N + c) = __floats2half2_rn(vx, vy);
            }
        }
    }
}

// ---------------- LayerNorm (float in, half out) ----------------
__global__ void ln_kernel(const float* __restrict__ x, const float* __restrict__ g,
                          const float* __restrict__ b, __half* __restrict__ out) {
    int row = blockIdx.x;
    int tid = threadIdx.x;
    const float4* xr = (const float4*)(x + (size_t)row * DD);
    float4 v = xr[tid];
    float s  = v.x + v.y + v.z + v.w;
    float ss = v.x*v.x + v.y*v.y + v.z*v.z + v.w*v.w;
    #pragma unroll
    for (int o = 16; o; o >>= 1) {
        s  += __shfl_xor_sync(0xffffffffu, s,  o);
        ss += __shfl_xor_sync(0xffffffffu, ss, o);
    }
    __shared__ float sm[8], sm2[8];
    int w = tid >> 5, l = tid & 31;
    if (l == 0) { sm[w] = s; sm2[w] = ss; }
    __syncthreads();
    float tot = 0.f, tot2 = 0.f;
    #pragma unroll
    for (int i = 0; i < 8; i++) { tot += sm[i]; tot2 += sm2[i]; }
    float mean = tot * (1.0f / DD);
    float var  = tot2 * (1.0f / DD) - mean * mean;
    float rstd = rsqrtf(var + 1e-5f);
    float4 gg = ((const float4*)g)[tid];
    float4 bb = ((const float4*)b)[tid];
    __half2 h0 = __floats2half2_rn((v.x - mean) * rstd * gg.x + bb.x,
                                   (v.y - mean) * rstd * gg.y + bb.y);
    __half2 h1 = __floats2half2_rn((v.z - mean) * rstd * gg.z + bb.z,
                                   (v.w - mean) * rstd * gg.w + bb.w);
    uint2 u;
    u.x = *(uint32_t*)&h0; u.y = *(uint32_t*)&h1;
    ((uint2*)(out + (size_t)row * DD))[tid] = u;
}

// ---------------- convert ALL weights float -> half (one kernel) ----------------
#define CVT_N0 786432
#define CVT_N1 (CVT_N0 + 262144)
#define CVT_N2 (CVT_N1 + 1048576)
#define CVT_N3 (CVT_N2 + 1048576)
__global__ void cvt_all_kernel(const float* __restrict__ w_in, const float* __restrict__ w_out,
                               const float* __restrict__ w1, const float* __restrict__ w2,
                               __half* __restrict__ oh) {
    int i = blockIdx.x * blockDim.x + threadIdx.x;
    if (i >= CVT_N3) return;
    const float* src; int j;
    if (i < CVT_N0)      { src = w_in;  j = i; }
    else if (i < CVT_N1) { src = w_out; j = i - CVT_N0; }
    else if (i < CVT_N2) { src = w1;    j = i - CVT_N1; }
    else                 { src = w2;    j = i - CVT_N2; }
    float4 v = ((const float4*)src)[j];
    __half2 h0 = __floats2half2_rn(v.x, v.y);
    __half2 h1 = __floats2half2_rn(v.z, v.w);
    uint2 u; u.x = *(uint32_t*)&h0; u.y = *(uint32_t*)&h1;
    ((uint2*)oh)[i] = u;
}

// ---------------- split-K attention: double-buffered smem, 1 barrier/tile ------
// grid = 1024: bid = b*512 + h*32 + qt*4 + s
__global__ void __launch_bounds__(256)
attn_part_kernel(const __half* __restrict__ qbuf, const __half* __restrict__ kv,
                 float* __restrict__ po, float* __restrict__ pm, float* __restrict__ pl) {
    int bid = blockIdx.x;
    int s  = bid & 3;
    int qt = (bid >> 2) & 7;
    int h  = (bid >> 5) & 15;
    int b  = bid >> 9;

    __shared__ float Qs[32][68];
    __shared__ float Ks[2][32][68];
    __shared__ float Vs[2][32][68];
    __shared__ float S [32][36];

    int tid = threadIdx.x;
    int qi_ = tid >> 3, d8 = tid & 7;

    {
        int g = b * 256 + qt * 32 + qi_;
        uint4 u = *(const uint4*)(qbuf + (size_t)g * DD + h * HDIM + d8 * 8);
        const __half2* hp = (const __half2*)&u;
        #pragma unroll
        for (int j = 0; j < 4; j++) {
            float2 f = __half22float2(hp[j]);
            Qs[qi_][d8 * 8 + j * 2]     = f.x * 0.125f;
            Qs[qi_][d8 * 8 + j * 2 + 1] = f.y * 0.125f;
        }
    }

    const int kt0 = s * 16, kt1 = s * 16 + 16;

    // preload first K/V tile into registers
    uint4 rk, rv;
    {
        size_t base = (size_t)(b * TT + kt0 * 32 + qi_) * (2 * DD) + h * HDIM + d8 * 8;
        rk = *(const uint4*)(kv + base);
        rv = *(const uint4*)(kv + base + DD);
    }

    int qi = tid >> 3, sl = tid & 7;
    float mrun = -1e30f, lrun = 0.f;
    float oacc[8] = {};
    int p = 0;

    for (int kt = kt0; kt < kt1; kt++) {
        // store preloaded regs into buffer p
        {
            const __half2* kp = (const __half2*)&rk;
            const __half2* vp = (const __half2*)&rv;
            #pragma unroll
            for (int j = 0; j < 4; j++) {
                float2 fk = __half22float2(kp[j]);
                float2 fv = __half22float2(vp[j]);
                Ks[p][qi_][d8 * 8 + j * 2] = fk.x;  Ks[p][qi_][d8 * 8 + j * 2 + 1] = fk.y;
                Vs[p][qi_][d8 * 8 + j * 2] = fv.x;  Vs[p][qi_][d8 * 8 + j * 2 + 1] = fv.y;
            }
        }
        // preload next tile (hidden under compute by the scoreboard)
        if (kt + 1 < kt1) {
            size_t base = (size_t)(b * TT + (kt + 1) * 32 + qi_) * (2 * DD) + h * HDIM + d8 * 8;
            rk = *(const uint4*)(kv + base);
            rv = *(const uint4*)(kv + base + DD);
        }
        __syncthreads();

        float s4[4] = {0.f, 0.f, 0.f, 0.f};
        #pragma unroll
        for (int d4 = 0; d4 < 16; d4++) {
            float4 qv = *(const float4*)&Qs[qi][d4 * 4];
            #pragma unroll
            for (int kj = 0; kj < 4; kj++) {
                float4 kvv = *(const float4*)&Ks[p][kj * 8 + sl][d4 * 4];
                s4[kj] += qv.x * kvv.x + qv.y * kvv.y + qv.z * kvv.z + qv.w * kvv.w;
            }
        }
        float tmax = fmaxf(fmaxf(s4[0], s4[1]), fmaxf(s4[2], s4[3]));
        #pragma unroll
        for (int off = 4; off; off >>= 1)
            tmax = fmaxf(tmax, __shfl_xor_sync(0xffffffffu, tmax, off));
        float mnew = fmaxf(mrun, tmax);
        float psum = 0.f;
        #pragma unroll
        for (int kj = 0; kj < 4; kj++) {
            float pr = __expf(s4[kj] - mnew);
            psum += pr;
            S[qi][kj * 8 + sl] = pr;
        }
        #pragma unroll
        for (int off = 4; off; off >>= 1)
            psum += __shfl_xor_sync(0xffffffffu, psum, off);
        float factor = __expf(mrun - mnew);
        lrun = lrun * factor + psum;
        mrun = mnew;
        __syncwarp();

        #pragma unroll
        for (int j = 0; j < 8; j++) oacc[j] *= factor;
        #pragma unroll
        for (int key = 0; key < 32; key++) {
            float pr = S[qi][key];
            float4 v0 = *(const float4*)&Vs[p][key][sl * 8];
            float4 v1 = *(const float4*)&Vs[p][key][sl * 8 + 4];
            oacc[0] += pr * v0.x; oacc[1] += pr * v0.y;
            oacc[2] += pr * v0.z; oacc[3] += pr * v0.w;
            oacc[4] += pr * v1.x; oacc[5] += pr * v1.y;
            oacc[6] += pr * v1.z; oacc[7] += pr * v1.w;
        }
        p ^= 1;
    }

    float* pop = po + (size_t)bid * 2048 + qi * 64 + sl * 8;
    *(float4*)pop       = make_float4(oacc[0], oacc[1], oacc[2], oacc[3]);
    *(float4*)(pop + 4) = make_float4(oacc[4], oacc[5], oacc[6], oacc[7]);
    if (sl == 0) {
        pm[bid * 32 + qi] = mrun;
        pl[bid * 32 + qi] = lrun;
    }
}

// ---------------- combine 4 split partials -> o (half) ----------------
__global__ void attn_combine_kernel(const float* __restrict__ po, const float* __restrict__ pm,
                                    const float* __restrict__ pl, __half* __restrict__ o) {
    int g = blockIdx.x * blockDim.x + threadIdx.x;
    int d8 = g & 7;
    int qi = (g >> 3) & 31;
    int qt = (g >> 8) & 7;
    int h  = (g >> 11) & 15;
    int b  = g >> 15;

    int bid0 = b * 512 + h * 32 + qt * 4;
    float m0 = pm[(bid0 + 0) * 32 + qi], m1 = pm[(bid0 + 1) * 32 + qi];
    float m2 = pm[(bid0 + 2) * 32 + qi], m3 = pm[(bid0 + 3) * 32 + qi];
    float mm = fmaxf(fmaxf(m0, m1), fmaxf(m2, m3));
    float e0 = __expf(m0 - mm), e1 = __expf(m1 - mm);
    float e2 = __expf(m2 - mm), e3 = __expf(m3 - mm);
    float denom = e0 * pl[(bid0 + 0) * 32 + qi] + e1 * pl[(bid0 + 1) * 32 + qi]
                + e2 * pl[(bid0 + 2) * 32 + qi] + e3 * pl[(bid0 + 3) * 32 + qi];
    float inv = 1.0f / denom;

    const float* p0 = po + (size_t)(bid0 + 0) * 2048 + qi * 64 + d8 * 8;
    const float* p1 = po + (size_t)(bid0 + 1) * 2048 + qi * 64 + d8 * 8;
    const float* p2 = po + (size_t)(bid0 + 2) * 2048 + qi * 64 + d8 * 8;
    const float* p3 = po + (size_t)(bid0 + 3) * 2048 + qi * 64 + d8 * 8;

    float res[8];
    #pragma unroll
    for (int j = 0; j < 8; j++)
        res[j] = (e0 * p0[j] + e1 * p1[j] + e2 * p2[j] + e3 * p3[j]) * inv;

    int t = (qt * 32 + qi) * QSTRIDE;
    __half2 h0 = __floats2half2_rn(res[0], res[1]);
    __half2 h1 = __floats2half2_rn(res[2], res[3]);
    __half2 h2 = __floats2half2_rn(res[4], res[5]);
    __half2 h3 = __floats2half2_rn(res[6], res[7]);
    uint4 u;
    u.x = *(uint32_t*)&h0; u.y = *(uint32_t*)&h1;
    u.z = *(uint32_t*)&h2; u.w = *(uint32_t*)&h3;
    *(uint4*)(o + (size_t)(b * TT + t) * DD + h * HDIM + d8 * 8) = u;
}

// ---------------- launch ----------------
extern "C" void kernel_launch(void* const* d_in, const int* in_sizes, int n_in,
                              void* d_out, int out_size) {
    const float* x     = (const float*)d_in[0];
    const float* w_in  = (const float*)d_in[1];
    const float* b_in  = (const float*)d_in[2];
    const float* w_out = (const float*)d_in[3];
    const float* b_out = (const float*)d_in[4];
    const float* w1    = (const float*)d_in[5];
    const float* b1    = (const float*)d_in[6];
    const float* w2    = (const float*)d_in[7];
    const float* b2    = (const float*)d_in[8];
    const float* ln1g  = (const float*)d_in[9];
    const float* ln1b  = (const float*)d_in[10];
    const float* ln2g  = (const float*)d_in[11];
    const float* ln2b  = (const float*)d_in[12];
    float* out = (float*)d_out;

    __half *xn, *kvb, *qb, *o, *hbuf, *wh;
    float *x1, *po, *pm, *pl;
    cudaGetSymbolAddress((void**)&xn,   g_xn);
    cudaGetSymbolAddress((void**)&kvb,  g_kv);
    cudaGetSymbolAddress((void**)&qb,   g_q);
    cudaGetSymbolAddress((void**)&o,    g_o);
    cudaGetSymbolAddress((void**)&hbuf, g_h);
    cudaGetSymbolAddress((void**)&x1,   g_x1);
    cudaGetSymbolAddress((void**)&wh,   g_wh);
    cudaGetSymbolAddress((void**)&po,   g_po);
    cudaGetSymbolAddress((void**)&pm,   g_pm);
    cudaGetSymbolAddress((void**)&pl,   g_pl);
    __half* wh_q   = wh;
    __half* wh_kv  = wh + (size_t)DD*DD;
    __half* wh_out = wh + (size_t)3*1024*1024;
    __half* wh_1   = wh + (size_t)4*1024*1024;
    __half* wh_2   = wh + (size_t)8*1024*1024;

    cudaFuncSetAttribute(hgemm<0>, cudaFuncAttributeMaxDynamicSharedMemorySize, SMEM_TOT);
    cudaFuncSetAttribute(hgemm<1>, cudaFuncAttributeMaxDynamicSharedMemorySize, SMEM_TOT);
    cudaFuncSetAttribute(hgemm<2>, cudaFuncAttributeMaxDynamicSharedMemorySize, SMEM_TOT);
    cudaFuncSetAttribute(qgemm,    cudaFuncAttributeMaxDynamicSharedMemorySize, SMEM_TOT);

    // second stream + events for graph-branch overlap (created per call; never
    // destroyed — kernel_launch runs only twice on host, so no meaningful leak,
    // and destroying a forked stream mid-capture is illegal)
    cudaStream_t s2;
    cudaStreamCreateWithFlags(&s2, cudaStreamNonBlocking);
    cudaEvent_t eFork, eCvt, eLn, eQ;
    cudaEventCreateWithFlags(&eFork, cudaEventDisableTiming);
    cudaEventCreateWithFlags(&eCvt,  cudaEventDisableTiming);
    cudaEventCreateWithFlags(&eLn,   cudaEventDisableTiming);
    cudaEventCreateWithFlags(&eQ,    cudaEventDisableTiming);

    // fork s2 off the main (capture) stream
    cudaEventRecord(eFork, 0);
    cudaStreamWaitEvent(s2, eFork, 0);

    // s2: weight conversion           main: LN1
    cvt_all_kernel<<<(CVT_N3 + 255)/256, 256, 0, s2>>>(w_in, w_out, w1, w2, wh);
    ln_kernel<<<NTOK, 256>>>(x, ln1g, ln1b, xn);
    cudaEventRecord(eCvt, s2);
    cudaEventRecord(eLn, 0);

    // s2: qgemm (needs cvt + ln1)     main: kv hgemm (needs cvt + ln1)
    cudaStreamWaitEvent(s2, eLn, 0);
    qgemm<<<dim3(DD/128, NGLOB/128), 256, SMEM_TOT, s2>>>(xn, wh_q, b_in, qb);
    cudaEventRecord(eQ, s2);
    cudaStreamWaitEvent(0, eCvt, 0);
    hgemm<0><<<dim3(2*DD/128, NTOK/128), 256, SMEM_TOT>>>(
        xn, wh_kv, b_in + DD, nullptr, kvb, o, NTOK, 2*DD, DD);

    // join: attention needs qgemm (s2) + kv (main)
    cudaStreamWaitEvent(0, eQ, 0);
    attn_part_kernel<<<NABLK, 256>>>(qb, kvb, po, pm, pl);
    attn_combine_kernel<<<65536/256, 256>>>(po, pm, pl, o);
    // x1 = o @ w_out.T + b_out + x
    hgemm<1><<<dim3(DD/128, NTOK/128), 256, SMEM_TOT>>>(
        o, wh_out, b_out, x, x1, nullptr, NTOK, DD, DD);
    // LN2
    ln_kernel<<<NTOK, 256>>>(x1, ln2g, ln2b, xn);
    // h = gelu(xn @ w1.T + b1)
    hgemm<2><<<dim3(MLPD/128, NTOK/128), 256, SMEM_TOT>>>(
        xn, wh_1, b1, nullptr, hbuf, nullptr, NTOK, MLPD, DD);
    // out = h @ w2.T + b2 + x1
    hgemm<1><<<dim3(DD/128, NTOK/128), 256, SMEM_TOT>>>(
        hbuf, wh_2, b2, x1, out, nullptr, NTOK, DD, MLPD);
}

// round 16
// speedup vs baseline: 3.3518x; 1.9278x over previous
#include <cuda_runtime.h>
#include <cuda_fp16.h>
#include <cstdint>

#define BB 2
#define TT 2048
#define DD 1024
#define HH 16
#define HDIM 64
#define QSTRIDE 8
#define MLPD 4096
#define NTOK (BB*TT)   // 4096
#define NGLOB (NTOK/QSTRIDE)   // 512
#define NSPLIT 8
#define NABLK (BB*HH*2*NSPLIT)  // 512 attention blocks (128 queries each)

// ---------------- scratch ----------------
__device__ __half g_xn[(size_t)NTOK*DD];
__device__ __half g_kv[(size_t)NTOK*2*DD];
__device__ __half g_q[(size_t)NGLOB*DD];
__device__ __half g_o[(size_t)NTOK*DD];
__device__ __half g_h[(size_t)NTOK*MLPD];
__device__ float  g_x1[(size_t)NTOK*DD];
__device__ __half g_wh[(size_t)12*1024*1024];
__device__ float  g_po[(size_t)NABLK*128*64];   // split-K partials (16.8 MB)
__device__ float  g_pm[(size_t)NABLK*128];
__device__ float  g_pl[(size_t)NABLK*128];

// ---------------- helpers ----------------
__device__ __forceinline__ uint32_t smem_u32(const void* p) {
    uint32_t a;
    asm("{ .reg .u64 t; cvta.to.shared.u64 t, %1; cvt.u32.u64 %0, t; }" : "=r"(a) : "l"(p));
    return a;
}
#define CP_ASYNC16(dst, src) \
    asm volatile("cp.async.cg.shared.global [%0], [%1], 16;" :: "r"(dst), "l"(src) : "memory")
#define CP_COMMIT() asm volatile("cp.async.commit_group;" ::: "memory")
#define CP_WAIT0() asm volatile("cp.async.wait_group 0;" ::: "memory")
#define CP_WAIT1() asm volatile("cp.async.wait_group 1;" ::: "memory")

#define LDSM_X4(r0, r1, r2, r3, addr) \
    asm volatile("ldmatrix.sync.aligned.m8n8.x4.shared.b16 {%0,%1,%2,%3}, [%4];" \
        : "=r"(r0), "=r"(r1), "=r"(r2), "=r"(r3) : "r"(addr))
#define LDSM_X4_T(r0, r1, r2, r3, addr) \
    asm volatile("ldmatrix.sync.aligned.m8n8.x4.trans.shared.b16 {%0,%1,%2,%3}, [%4];" \
        : "=r"(r0), "=r"(r1), "=r"(r2), "=r"(r3) : "r"(addr))

__device__ __forceinline__ void mma_f16(float* d, const uint32_t* a, const uint32_t* b) {
    asm volatile(
        "mma.sync.aligned.m16n8k16.row.col.f32.f16.f16.f32 "
        "{%0,%1,%2,%3}, {%4,%5,%6,%7}, {%8,%9}, {%0,%1,%2,%3};"
        : "+f"(d[0]), "+f"(d[1]), "+f"(d[2]), "+f"(d[3])
        : "r"(a[0]), "r"(a[1]), "r"(a[2]), "r"(a[3]), "r"(b[0]), "r"(b[1]));
}

// ---------------- fp16 mma GEMM (R10 codegen, unchanged) ----------------------
#define ROWH 72
#define STG_B (128*ROWH*2)
#define STAGE_B (2*STG_B)
#define NSTG 3
#define SMEM_TOT (NSTG*STAGE_B)         // 110592 B -> 2 CTAs/SM

template <int EPI>
__global__ void __launch_bounds__(256, 2)
hgemm(const __half* __restrict__ A, const __half* __restrict__ W,
      const float* __restrict__ bias, const float* __restrict__ res,
      void* __restrict__ Cv, __half* __restrict__ vout, int M, int N, int K)
{
    extern __shared__ __half smem[];
    uint32_t sbase = smem_u32(smem);
    int tid = threadIdx.x;
    int wid = tid >> 5, lane = tid & 31;
    int gp = lane >> 2, tc = lane & 3;
    int m0 = blockIdx.y * 128, n0 = blockIdx.x * 128;
    int wm = (wid & 1) * 64;
    int wn = (wid >> 1) * 32;

    int a_row = lane & 15;
    int a_k8  = (lane >> 4) * 8;
    int b_grp = lane >> 3;
    int b_row = lane & 7;
    int b_nof = (b_grp >> 1) * 8 + b_row;
    int b_k8  = (b_grp & 1) * 8;

    float acc[4][4][4];
    #pragma unroll
    for (int i = 0; i < 4; i++)
        #pragma unroll
        for (int j = 0; j < 4; j++)
            #pragma unroll
            for (int k = 0; k < 4; k++) acc[i][j][k] = 0.f;

    const int KT = K >> 6;

    auto load_tile = [&](int s, int kt) {
        uint32_t sa = sbase + s * STAGE_B;
        uint32_t sb = sa + STG_B;
        const __half* Ag = A + (size_t)m0 * K + kt * 64;
        const __half* Wg = W + (size_t)n0 * K + kt * 64;
        #pragma unroll
        for (int i = 0; i < 4; i++) {
            int idx = i * 256 + tid;
            int row = idx >> 3, ch = idx & 7;
            CP_ASYNC16(sa + (row * ROWH + ch * 8) * 2, Ag + (size_t)row * K + ch * 8);
        }
        #pragma unroll
        for (int i = 0; i < 4; i++) {
            int idx = i * 256 + tid;
            int row = idx >> 3, ch = idx & 7;
            CP_ASYNC16(sb + (row * ROWH + ch * 8) * 2, Wg + (size_t)row * K + ch * 8);
        }
        CP_COMMIT();
    };

    load_tile(0, 0);
    load_tile(1, 1);

    for (int kt = 0; kt < KT; kt++) {
        if (kt + 1 < KT) { CP_WAIT1(); } else { CP_WAIT0(); }
        __syncthreads();
        if (kt + 2 < KT) load_tile((kt + 2) % NSTG, kt + 2);

        uint32_t sa = sbase + (kt % NSTG) * STAGE_B;
        uint32_t sb = sa + STG_B;

        #pragma unroll
        for (int ks = 0; ks < 4; ks++) {
            uint32_t af[4][4], bf[2][4];
            #pragma unroll
            for (int mt = 0; mt < 4; mt++)
                LDSM_X4(af[mt][0], af[mt][1], af[mt][2], af[mt][3],
                        sa + ((wm + mt * 16 + a_row) * ROWH + ks * 16 + a_k8) * 2);
            #pragma unroll
            for (int p = 0; p < 2; p++)
                LDSM_X4(bf[p][0], bf[p][1], bf[p][2], bf[p][3],
                        sb + ((wn + p * 16 + b_nof) * ROWH + ks * 16 + b_k8) * 2);
            #pragma unroll
            for (int mt = 0; mt < 4; mt++)
                #pragma unroll
                for (int nt = 0; nt < 4; nt++)
                    mma_f16(acc[mt][nt], af[mt], &bf[nt >> 1][(nt & 1) * 2]);
        }
    }

    #pragma unroll
    for (int mt = 0; mt < 4; mt++) {
        int r0 = m0 + wm + mt * 16 + gp;
        #pragma unroll
        for (int nt = 0; nt < 4; nt++) {
            int c = n0 + wn + nt * 8 + 2 * tc;
            float bx = bias[c], by = bias[c + 1];
            #pragma unroll
            for (int half_ = 0; half_ < 2; half_++) {
                int r = r0 + half_ * 8;
                float vx = acc[mt][nt][half_ * 2 + 0] + bx;
                float vy = acc[mt][nt][half_ * 2 + 1] + by;
                size_t off = (size_t)r * N + c;
                if (EPI == 1) {
                    float2 rr = *(const float2*)(res + off);
                    vx += rr.x; vy += rr.y;
                    float2 o2; o2.x = vx; o2.y = vy;
                    *(float2*)((float*)Cv + off) = o2;
                } else {
                    if (EPI == 2) {
                        vx = 0.5f * vx * (1.0f + erff(vx * 0.70710678118f));
                        vy = 0.5f * vy * (1.0f + erff(vy * 0.70710678118f));
                    }
                    __half2 hv = __floats2half2_rn(vx, vy);
                    *(__half2*)((__half*)Cv + off) = hv;
                    if (EPI == 0 && vout != nullptr && c >= DD) {
                        *(__half2*)(vout + (size_t)r * DD + (c - DD)) = hv;
                    }
                }
            }
        }
    }
}

// ---------------- standalone Q GEMM (epilogue now folds the 1/8 softmax scale) -
__global__ void __launch_bounds__(256, 2)
qgemm(const __half* __restrict__ A, const __half* __restrict__ W,
      const float* __restrict__ bias, __half* __restrict__ C)
{
    extern __shared__ __half smem[];
    uint32_t sbase = smem_u32(smem);
    const int K = DD, N = DD;
    int tid = threadIdx.x;
    int wid = tid >> 5, lane = tid & 31;
    int gp = lane >> 2, tc = lane & 3;
    int m0 = blockIdx.y * 128, n0 = blockIdx.x * 128;
    int wm = (wid & 1) * 64;
    int wn = (wid >> 1) * 32;

    int a_row = lane & 15;
    int a_k8  = (lane >> 4) * 8;
    int b_grp = lane >> 3;
    int b_row = lane & 7;
    int b_nof = (b_grp >> 1) * 8 + b_row;
    int b_k8  = (b_grp & 1) * 8;

    float acc[4][4][4];
    #pragma unroll
    for (int i = 0; i < 4; i++)
        #pragma unroll
        for (int j = 0; j < 4; j++)
            #pragma unroll
            for (int k = 0; k < 4; k++) acc[i][j][k] = 0.f;

    const int KT = K >> 6;

    auto load_tile = [&](int s, int kt) {
        uint32_t sa = sbase + s * STAGE_B;
        uint32_t sb = sa + STG_B;
        const __half* Ag = A + kt * 64;
        const __half* Wg = W + (size_t)n0 * K + kt * 64;
        #pragma unroll
        for (int i = 0; i < 4; i++) {
            int idx = i * 256 + tid;
            int row = idx >> 3, ch = idx & 7;
            CP_ASYNC16(sa + (row * ROWH + ch * 8) * 2,
                       Ag + (size_t)(m0 + row) * (QSTRIDE * DD) + ch * 8);
        }
        #pragma unroll
        for (int i = 0; i < 4; i++) {
            int idx = i * 256 + tid;
            int row = idx >> 3, ch = idx & 7;
            CP_ASYNC16(sb + (row * ROWH + ch * 8) * 2, Wg + (size_t)row * K + ch * 8);
        }
        CP_COMMIT();
    };

    load_tile(0, 0);
    load_tile(1, 1);

    for (int kt = 0; kt < KT; kt++) {
        if (kt + 1 < KT) { CP_WAIT1(); } else { CP_WAIT0(); }
        __syncthreads();
        if (kt + 2 < KT) load_tile((kt + 2) % NSTG, kt + 2);

        uint32_t sa = sbase + (kt % NSTG) * STAGE_B;
        uint32_t sb = sa + STG_B;

        #pragma unroll
        for (int ks = 0; ks < 4; ks++) {
            uint32_t af[4][4], bf[2][4];
            #pragma unroll
            for (int mt = 0; mt < 4; mt++)
                LDSM_X4(af[mt][0], af[mt][1], af[mt][2], af[mt][3],
                        sa + ((wm + mt * 16 + a_row) * ROWH + ks * 16 + a_k8) * 2);
            #pragma unroll
            for (int p = 0; p < 2; p++)
                LDSM_X4(bf[p][0], bf[p][1], bf[p][2], bf[p][3],
                        sb + ((wn + p * 16 + b_nof) * ROWH + ks * 16 + b_k8) * 2);
            #pragma unroll
            for (int mt = 0; mt < 4; mt++)
                #pragma unroll
                for (int nt = 0; nt < 4; nt++)
                    mma_f16(acc[mt][nt], af[mt], &bf[nt >> 1][(nt & 1) * 2]);
        }
    }

    #pragma unroll
    for (int mt = 0; mt < 4; mt++) {
        int r0 = m0 + wm + mt * 16 + gp;
        #pragma unroll
        for (int nt = 0; nt < 4; nt++) {
            int c = n0 + wn + nt * 8 + 2 * tc;
            float bx = bias[c], by = bias[c + 1];
            #pragma unroll
            for (int half_ = 0; half_ < 2; half_++) {
                int r = r0 + half_ * 8;
                float vx = (acc[mt][nt][half_ * 2 + 0] + bx) * 0.125f;  // fold 1/sqrt(64)
                float vy = (acc[mt][nt][half_ * 2 + 1] + by) * 0.125f;
                *(__half2*)(C + (size_t)r * N + c) = __floats2half2_rn(vx, vy);
            }
        }
    }
}

// ---------------- LayerNorm (float in, half out) ----------------
__global__ void ln_kernel(const float* __restrict__ x, const float* __restrict__ g,
                          const float* __restrict__ b, __half* __restrict__ out) {
    int row = blockIdx.x;
    int tid = threadIdx.x;
    const float4* xr = (const float4*)(x + (size_t)row * DD);
    float4 v = xr[tid];
    float s  = v.x + v.y + v.z + v.w;
    float ss = v.x*v.x + v.y*v.y + v.z*v.z + v.w*v.w;
    #pragma unroll
    for (int o = 16; o; o >>= 1) {
        s  += __shfl_xor_sync(0xffffffffu, s,  o);
        ss += __shfl_xor_sync(0xffffffffu, ss, o);
    }
    __shared__ float sm[8], sm2[8];
    int w = tid >> 5, l = tid & 31;
    if (l == 0) { sm[w] = s; sm2[w] = ss; }
    __syncthreads();
    float tot = 0.f, tot2 = 0.f;
    #pragma unroll
    for (int i = 0; i < 8; i++) { tot += sm[i]; tot2 += sm2[i]; }
    float mean = tot * (1.0f / DD);
    float var  = tot2 * (1.0f / DD) - mean * mean;
    float rstd = rsqrtf(var + 1e-5f);
    float4 gg = ((const float4*)g)[tid];
    float4 bb = ((const float4*)b)[tid];
    __half2 h0 = __floats2half2_rn((v.x - mean) * rstd * gg.x + bb.x,
                                   (v.y - mean) * rstd * gg.y + bb.y);
    __half2 h1 = __floats2half2_rn((v.z - mean) * rstd * gg.z + bb.z,
                                   (v.w - mean) * rstd * gg.w + bb.w);
    uint2 u;
    u.x = *(uint32_t*)&h0; u.y = *(uint32_t*)&h1;
    ((uint2*)(out + (size_t)row * DD))[tid] = u;
}

// ---------------- convert ALL weights float -> half ----------------
#define CVT_N0 786432
#define CVT_N1 (CVT_N0 + 262144)
#define CVT_N2 (CVT_N1 + 1048576)
#define CVT_N3 (CVT_N2 + 1048576)
__global__ void cvt_all_kernel(const float* __restrict__ w_in, const float* __restrict__ w_out,
                               const float* __restrict__ w1, const float* __restrict__ w2,
                               __half* __restrict__ oh) {
    int i = blockIdx.x * blockDim.x + threadIdx.x;
    if (i >= CVT_N3) return;
    const float* src; int j;
    if (i < CVT_N0)      { src = w_in;  j = i; }
    else if (i < CVT_N1) { src = w_out; j = i - CVT_N0; }
    else if (i < CVT_N2) { src = w1;    j = i - CVT_N1; }
    else                 { src = w2;    j = i - CVT_N2; }
    float4 v = ((const float4*)src)[j];
    __half2 h0 = __floats2half2_rn(v.x, v.y);
    __half2 h1 = __floats2half2_rn(v.z, v.w);
    uint2 u; u.x = *(uint32_t*)&h0; u.y = *(uint32_t*)&h1;
    ((uint2*)oh)[i] = u;
}

// ---------------- tensor-core split-K attention ----------------
// grid = 512: bid = ((b*16 + h)*2 + qh)*8 + s.  Each block: 128 queries x 256 keys.
// 8 warps: warp w owns queries [qh*128 + w*16, +16).  K/V smem double-buffered.
#define AROW 72   // padded halves per 64-half row
__global__ void __launch_bounds__(256, 2)
attn_part_kernel(const __half* __restrict__ qbuf, const __half* __restrict__ kv,
                 float* __restrict__ po, float* __restrict__ pm, float* __restrict__ pl) {
    int bid = blockIdx.x;
    int s  = bid & 7;
    int qh = (bid >> 3) & 1;
    int h  = (bid >> 4) & 15;
    int b  = bid >> 8;

    __shared__ __half Qs[128 * AROW];
    __shared__ __half Ks[2][32 * AROW];
    __shared__ __half Vs[2][32 * AROW];

    int tid = threadIdx.x;
    int wid = tid >> 5, lane = tid & 31;
    int gp = lane >> 2, tc = lane & 3;

    // cooperative Q fill (128 rows x 64 halves), already scaled by 1/8 in qgemm
    #pragma unroll
    for (int i = 0; i < 4; i++) {
        int idx = i * 256 + tid;          // 0..1023
        int r = idx >> 3, seg = idx & 7;
        uint4 u = *(const uint4*)(qbuf + (size_t)(b * 256 + qh * 128 + r) * DD + h * HDIM + seg * 8);
        *(uint4*)&Qs[r * AROW + seg * 8] = u;
    }

    // K/V register preload for tile 0
    int krow = tid >> 3, kseg = tid & 7;
    int key0 = s * 256;
    uint4 rk, rv;
    {
        size_t base = (size_t)(b * TT + key0 + krow) * (2 * DD) + h * HDIM + kseg * 8;
        rk = *(const uint4*)(kv + base);
        rv = *(const uint4*)(kv + base + DD);
    }
    __syncthreads();

    // Q fragments: 4 k-chunks x x4 (hgemm A convention)
    int a_row = lane & 15, a_k8 = (lane >> 4) * 8;
    int wq = wid * 16;
    uint32_t qf[4][4];
    #pragma unroll
    for (int kc = 0; kc < 4; kc++)
        LDSM_X4(qf[kc][0], qf[kc][1], qf[kc][2], qf[kc][3],
                smem_u32(&Qs[(wq + a_row) * AROW + kc * 16 + a_k8]));

    // ldmatrix B lane addressing (hgemm convention)
    int b_grp = lane >> 3, b_row = lane & 7;
    int b_nof = (b_grp >> 1) * 8 + b_row;
    int b_k8  = (b_grp & 1) * 8;
    // V trans lane addressing: row = koct*8 + b_row, col = doct*8
    int v_roff = (b_grp & 1) * 8 + b_row;
    int v_coff = (b_grp >> 1) * 8;

    float m2[2] = {-1e30f, -1e30f};
    float l2[2] = {0.f, 0.f};
    float o[8][4];
    #pragma unroll
    for (int j = 0; j < 8; j++)
        #pragma unroll
        for (int k = 0; k < 4; k++) o[j][k] = 0.f;

    int p = 0;
    for (int t = 0; t < 8; t++) {
        *(uint4*)&Ks[p][krow * AROW + kseg * 8] = rk;
        *(uint4*)&Vs[p][krow * AROW + kseg * 8] = rv;
        if (t + 1 < 8) {
            size_t base = (size_t)(b * TT + key0 + (t + 1) * 32 + krow) * (2 * DD) + h * HDIM + kseg * 8;
            rk = *(const uint4*)(kv + base);
            rv = *(const uint4*)(kv + base + DD);
        }
        __syncthreads();

        // S = Q @ K^T  (16q x 32k per warp)
        float sacc[4][4];
        #pragma unroll
        for (int nt = 0; nt < 4; nt++)
            #pragma unroll
            for (int k = 0; k < 4; k++) sacc[nt][k] = 0.f;
        #pragma unroll
        for (int ks = 0; ks < 4; ks++) {
            uint32_t kf[2][4];
            #pragma unroll
            for (int pp = 0; pp < 2; pp++)
                LDSM_X4(kf[pp][0], kf[pp][1], kf[pp][2], kf[pp][3],
                        smem_u32(&Ks[p][(pp * 16 + b_nof) * AROW + ks * 16 + b_k8]));
            #pragma unroll
            for (int nt = 0; nt < 4; nt++)
                mma_f16(sacc[nt], qf[ks], &kf[nt >> 1][(nt & 1) * 2]);
        }

        // online softmax (rows gp and gp+8)
        float rm0 = -1e30f, rm1 = -1e30f;
        #pragma unroll
        for (int nt = 0; nt < 4; nt++) {
            rm0 = fmaxf(rm0, fmaxf(sacc[nt][0], sacc[nt][1]));
            rm1 = fmaxf(rm1, fmaxf(sacc[nt][2], sacc[nt][3]));
        }
        #pragma unroll
        for (int off = 1; off < 4; off <<= 1) {
            rm0 = fmaxf(rm0, __shfl_xor_sync(0xffffffffu, rm0, off));
            rm1 = fmaxf(rm1, __shfl_xor_sync(0xffffffffu, rm1, off));
        }
        float mn0 = fmaxf(m2[0], rm0), mn1 = fmaxf(m2[1], rm1);
        float ps0 = 0.f, ps1 = 0.f;
        #pragma unroll
        for (int nt = 0; nt < 4; nt++) {
            sacc[nt][0] = __expf(sacc[nt][0] - mn0);
            sacc[nt][1] = __expf(sacc[nt][1] - mn0);
            sacc[nt][2] = __expf(sacc[nt][2] - mn1);
            sacc[nt][3] = __expf(sacc[nt][3] - mn1);
            ps0 += sacc[nt][0] + sacc[nt][1];
            ps1 += sacc[nt][2] + sacc[nt][3];
        }
        #pragma unroll
        for (int off = 1; off < 4; off <<= 1) {
            ps0 += __shfl_xor_sync(0xffffffffu, ps0, off);
            ps1 += __shfl_xor_sync(0xffffffffu, ps1, off);
        }
        float f0 = __expf(m2[0] - mn0), f1 = __expf(m2[1] - mn1);
        l2[0] = l2[0] * f0 + ps0;  l2[1] = l2[1] * f1 + ps1;
        m2[0] = mn0;  m2[1] = mn1;
        #pragma unroll
        for (int j = 0; j < 8; j++) {
            o[j][0] *= f0; o[j][1] *= f0; o[j][2] *= f1; o[j][3] *= f1;
        }

        // P -> A fragments (canonical C->A relayout), 2 k16 chunks
        uint32_t pa[2][4];
        #pragma unroll
        for (int kc = 0; kc < 2; kc++) {
            __half2 t0 = __floats2half2_rn(sacc[kc*2+0][0], sacc[kc*2+0][1]);
            __half2 t1 = __floats2half2_rn(sacc[kc*2+0][2], sacc[kc*2+0][3]);
            __half2 t2 = __floats2half2_rn(sacc[kc*2+1][0], sacc[kc*2+1][1]);
            __half2 t3 = __floats2half2_rn(sacc[kc*2+1][2], sacc[kc*2+1][3]);
            pa[kc][0] = *(uint32_t*)&t0; pa[kc][1] = *(uint32_t*)&t1;
            pa[kc][2] = *(uint32_t*)&t2; pa[kc][3] = *(uint32_t*)&t3;
        }

        // O += P @ V   (16q x 64d, k=32)
        #pragma unroll
        for (int dr = 0; dr < 4; dr++) {
            uint32_t vb[2][4];
            #pragma unroll
            for (int kc = 0; kc < 2; kc++)
                LDSM_X4_T(vb[kc][0], vb[kc][1], vb[kc][2], vb[kc][3],
                          smem_u32(&Vs[p][(kc * 16 + v_roff) * AROW + dr * 16 + v_coff]));
            #pragma unroll
            for (int kc = 0; kc < 2; kc++)
                #pragma unroll
                for (int j = 0; j < 2; j++)
                    mma_f16(o[dr * 2 + j], pa[kc], &vb[kc][j * 2]);
        }
        p ^= 1;
    }

    // write unnormalized partials
    float* base = po + (size_t)bid * (128 * 64);
    #pragma unroll
    for (int j = 0; j < 8; j++) {
        float2 lo; lo.x = o[j][0]; lo.y = o[j][1];
        float2 hi; hi.x = o[j][2]; hi.y = o[j][3];
        *(float2*)(base + (wq + gp) * 64 + j * 8 + 2 * tc)     = lo;
        *(float2*)(base + (wq + gp + 8) * 64 + j * 8 + 2 * tc) = hi;
    }
    if (tc == 0) {
        pm[bid * 128 + wq + gp]     = m2[0];
        pm[bid * 128 + wq + gp + 8] = m2[1];
        pl[bid * 128 + wq + gp]     = l2[0];
        pl[bid * 128 + wq + gp + 8] = l2[1];
    }
}

// ---------------- combine 8 split partials -> o (half) ----------------
__global__ void attn_combine_kernel(const float* __restrict__ po, const float* __restrict__ pm,
                                    const float* __restrict__ pl, __half* __restrict__ o) {
    int g = blockIdx.x * blockDim.x + threadIdx.x;   // 65536
    int d8 = g & 7;
    int qc = (g >> 3) & 255;
    int h  = (g >> 11) & 15;
    int b  = g >> 15;

    int bid0 = ((b * 16 + h) * 2 + (qc >> 7)) * 8;
    int ql = qc & 127;

    float mm = -1e30f;
    float ms[NSPLIT];
    #pragma unroll
    for (int s = 0; s < NSPLIT; s++) {
        ms[s] = pm[(bid0 + s) * 128 + ql];
        mm = fmaxf(mm, ms[s]);
    }
    float denom = 0.f;
    float es[NSPLIT];
    #pragma unroll
    for (int s = 0; s < NSPLIT; s++) {
        es[s] = __expf(ms[s] - mm);
        denom += es[s] * pl[(bid0 + s) * 128 + ql];
    }
    float inv = 1.0f / denom;

    float res[8] = {};
    #pragma unroll
    for (int s = 0; s < NSPLIT; s++) {
        const float* pp = po + (size_t)(bid0 + s) * (128 * 64) + ql * 64 + d8 * 8;
        #pragma unroll
        for (int j = 0; j < 8; j++) res[j] += es[s] * pp[j];
    }
    #pragma unroll
    for (int j = 0; j < 8; j++) res[j] *= inv;

    int t = qc * QSTRIDE;
    __half2 h0 = __floats2half2_rn(res[0], res[1]);
    __half2 h1 = __floats2half2_rn(res[2], res[3]);
    __half2 h2 = __floats2half2_rn(res[4], res[5]);
    __half2 h3 = __floats2half2_rn(res[6], res[7]);
    uint4 u;
    u.x = *(uint32_t*)&h0; u.y = *(uint32_t*)&h1;
    u.z = *(uint32_t*)&h2; u.w = *(uint32_t*)&h3;
    *(uint4*)(o + (size_t)(b * TT + t) * DD + h * HDIM + d8 * 8) = u;
}

// ---------------- launch ----------------
extern "C" void kernel_launch(void* const* d_in, const int* in_sizes, int n_in,
                              void* d_out, int out_size) {
    const float* x     = (const float*)d_in[0];
    const float* w_in  = (const float*)d_in[1];
    const float* b_in  = (const float*)d_in[2];
    const float* w_out = (const float*)d_in[3];
    const float* b_out = (const float*)d_in[4];
    const float* w1    = (const float*)d_in[5];
    const float* b1    = (const float*)d_in[6];
    const float* w2    = (const float*)d_in[7];
    const float* b2    = (const float*)d_in[8];
    const float* ln1g  = (const float*)d_in[9];
    const float* ln1b  = (const float*)d_in[10];
    const float* ln2g  = (const float*)d_in[11];
    const float* ln2b  = (const float*)d_in[12];
    float* out = (float*)d_out;

    __half *xn, *kvb, *qb, *o, *hbuf, *wh;
    float *x1, *po, *pm, *pl;
    cudaGetSymbolAddress((void**)&xn,   g_xn);
    cudaGetSymbolAddress((void**)&kvb,  g_kv);
    cudaGetSymbolAddress((void**)&qb,   g_q);
    cudaGetSymbolAddress((void**)&o,    g_o);
    cudaGetSymbolAddress((void**)&hbuf, g_h);
    cudaGetSymbolAddress((void**)&x1,   g_x1);
    cudaGetSymbolAddress((void**)&wh,   g_wh);
    cudaGetSymbolAddress((void**)&po,   g_po);
    cudaGetSymbolAddress((void**)&pm,   g_pm);
    cudaGetSymbolAddress((void**)&pl,   g_pl);
    __half* wh_q   = wh;
    __half* wh_kv  = wh + (size_t)DD*DD;
    __half* wh_out = wh + (size_t)3*1024*1024;
    __half* wh_1   = wh + (size_t)4*1024*1024;
    __half* wh_2   = wh + (size_t)8*1024*1024;

    cudaFuncSetAttribute(hgemm<0>, cudaFuncAttributeMaxDynamicSharedMemorySize, SMEM_TOT);
    cudaFuncSetAttribute(hgemm<1>, cudaFuncAttributeMaxDynamicSharedMemorySize, SMEM_TOT);
    cudaFuncSetAttribute(hgemm<2>, cudaFuncAttributeMaxDynamicSharedMemorySize, SMEM_TOT);
    cudaFuncSetAttribute(qgemm,    cudaFuncAttributeMaxDynamicSharedMemorySize, SMEM_TOT);

    cudaStream_t s2;
    cudaStreamCreateWithFlags(&s2, cudaStreamNonBlocking);
    cudaEvent_t eFork, eCvt, eLn, eQ;
    cudaEventCreateWithFlags(&eFork, cudaEventDisableTiming);
    cudaEventCreateWithFlags(&eCvt,  cudaEventDisableTiming);
    cudaEventCreateWithFlags(&eLn,   cudaEventDisableTiming);
    cudaEventCreateWithFlags(&eQ,    cudaEventDisableTiming);

    cudaEventRecord(eFork, 0);
    cudaStreamWaitEvent(s2, eFork, 0);

    // s2: weight conversion           main: LN1
    cvt_all_kernel<<<(CVT_N3 + 255)/256, 256, 0, s2>>>(w_in, w_out, w1, w2, wh);
    ln_kernel<<<NTOK, 256>>>(x, ln1g, ln1b, xn);
    cudaEventRecord(eCvt, s2);
    cudaEventRecord(eLn, 0);

    // s2: qgemm                        main: kv hgemm
    cudaStreamWaitEvent(s2, eLn, 0);
    qgemm<<<dim3(DD/128, NGLOB/128), 256, SMEM_TOT, s2>>>(xn, wh_q, b_in, qb);
    cudaEventRecord(eQ, s2);
    cudaStreamWaitEvent(0, eCvt, 0);
    hgemm<0><<<dim3(2*DD/128, NTOK/128), 256, SMEM_TOT>>>(
        xn, wh_kv, b_in + DD, nullptr, kvb, o, NTOK, 2*DD, DD);

    // join, attention
    cudaStreamWaitEvent(0, eQ, 0);
    attn_part_kernel<<<NABLK, 256>>>(qb, kvb, po, pm, pl);
    attn_combine_kernel<<<65536/256, 256>>>(po, pm, pl, o);
    // x1 = o @ w_out.T + b_out + x
    hgemm<1><<<dim3(DD/128, NTOK/128), 256, SMEM_TOT>>>(
        o, wh_out, b_out, x, x1, nullptr, NTOK, DD, DD);
    // LN2
    ln_kernel<<<NTOK, 256>>>(x1, ln2g, ln2b, xn);
    // h = gelu(xn @ w1.T + b1)
    hgemm<2><<<dim3(MLPD/128, NTOK/128), 256, SMEM_TOT>>>(
        xn, wh_1, b1, nullptr, hbuf, nullptr, NTOK, MLPD, DD);
    // out = h @ w2.T + b2 + x1
    hgemm<1><<<dim3(DD/128, NTOK/128), 256, SMEM_TOT>>>(
        hbuf, wh_2, b2, x1, out, nullptr, NTOK, DD, MLPD);
}